// round 12
// baseline (speedup 1.0000x reference)
#include <cuda_runtime.h>
#include <cuda_fp16.h>
#include <math.h>
#include <stdint.h>

#define B_   32
#define L_   512
#define D_   512
#define H_   8
#define DH_  64
#define NL_  2
#define DFF_ 2048
#define NB_  32
#define ML_  (B_*L_)   // 16384 rows
#define NQKV 1536

// ---------------- scratch (device globals; no allocations) ----------------
__device__ float g_x [ML_*D_];
__device__ float g_po[ML_*D_];
__device__ __align__(16) __half g_ah[ML_*D_];
__device__ __align__(16) __half g_fh[ML_*DFF_];
__device__ __align__(16) __half g_qv[ML_*NQKV];
#define WT_LAYER (4*512*512 + 2048*512 + 512*2048)
__device__ __align__(16) __half g_wth[NL_*WT_LAYER];
__device__ __align__(16) unsigned char g_bk[B_*L_*L_];
__device__ float g_bqkv[NL_*NQKV];

// ====================== PTX helpers ======================
__device__ __forceinline__ uint32_t smem_u32(const void* p) {
    uint32_t a;
    asm("{ .reg .u64 t; cvta.to.shared.u64 t, %1; cvt.u32.u64 %0, t; }" : "=r"(a) : "l"(p));
    return a;
}
__device__ __forceinline__ void cp16(uint32_t s, const void* g) {
    asm volatile("cp.async.cg.shared.global [%0], [%1], 16;" :: "r"(s), "l"(g));
}
__device__ __forceinline__ void ldsm4(uint32_t* r, uint32_t a) {
    asm volatile("ldmatrix.sync.aligned.m8n8.x4.shared.b16 {%0,%1,%2,%3}, [%4];"
        : "=r"(r[0]), "=r"(r[1]), "=r"(r[2]), "=r"(r[3]) : "r"(a));
}
__device__ __forceinline__ void ldsm4t(uint32_t* r, uint32_t a) {
    asm volatile("ldmatrix.sync.aligned.m8n8.x4.trans.shared.b16 {%0,%1,%2,%3}, [%4];"
        : "=r"(r[0]), "=r"(r[1]), "=r"(r[2]), "=r"(r[3]) : "r"(a));
}
__device__ __forceinline__ void mma16816h(float* c, const uint32_t* a, const uint32_t* b) {
    asm volatile("mma.sync.aligned.m16n8k16.row.col.f32.f16.f16.f32 "
        "{%0,%1,%2,%3}, {%4,%5,%6,%7}, {%8,%9}, {%0,%1,%2,%3};"
        : "+f"(c[0]), "+f"(c[1]), "+f"(c[2]), "+f"(c[3])
        : "r"(a[0]), "r"(a[1]), "r"(a[2]), "r"(a[3]), "r"(b[0]), "r"(b[1]));
}
__device__ __forceinline__ uint32_t pack_f16(float x, float y) {
    __half2 t = __halves2half2(__float2half_rn(x), __float2half_rn(y));
    return *(uint32_t*)&t;
}
__device__ __forceinline__ void store_f16x2(__half* O, size_t off, float v0, float v1) {
    *(uint32_t*)(O + off) = pack_f16(v0, v1);
}

// ====================== time bucket ======================
__device__ __forceinline__ int time_bucket(float delta)
{
    float a = fmaxf(fabsf(delta), 1.0f);
    const float scale = 0.71018780958489f;   // float32(log2(2592000)/30)
    int idx = (int)(log2f(a) / scale) + 1;
    idx = max(1, min(idx, NB_ - 2));
    if (a <= 1.0f)       idx = 0;
    if (a >= 2592000.0f) idx = NB_ - 1;
    return idx;
}

__global__ void bucket_kernel(const float* __restrict__ ts)
{
    int idx = blockIdx.x * blockDim.x + threadIdx.x;   // over B*L*L
    int k = idx & (L_-1);
    int q = (idx >> 9) & (L_-1);
    int b = idx >> 18;
    float d = ts[b * L_ + q] - ts[b * L_ + k];
    g_bk[idx] = (unsigned char)time_bucket(d);
}

__global__ void biascat_kernel(const float* __restrict__ bq,
                               const float* __restrict__ bk,
                               const float* __restrict__ bv)
{
    int i = blockIdx.x * blockDim.x + threadIdx.x;   // NL*1536
    int l = i / NQKV, c = i % NQKV;
    float v = (c < 512) ? bq[l*512 + c] : (c < 1024 ? bk[l*512 + c - 512] : bv[l*512 + c - 1024]);
    g_bqkv[i] = v;
}

// ====================== embedding (+ fp16) ======================
__global__ void embed_kernel(const int* __restrict__ seq,
                             const float* __restrict__ item_emb,
                             const float* __restrict__ pos_emb)
{
    int idx = blockIdx.x * blockDim.x + threadIdx.x;   // over ML*D/4
    int d4 = idx & (D_/4 - 1);
    int bl = idx >> 7;
    int l  = bl & (L_-1);
    int it = seq[bl];
    float4 a = *(const float4*)(item_emb + (size_t)it * D_ + d4*4);
    float4 p = *(const float4*)(pos_emb  + (size_t)l  * D_ + d4*4);
    a.x += p.x; a.y += p.y; a.z += p.z; a.w += p.w;
    ((float4*)g_x)[idx] = a;
    size_t off = (size_t)idx * 4;
    store_f16x2(g_ah, off,     a.x, a.y);
    store_f16x2(g_ah, off + 2, a.z, a.w);
}

// ====================== weight transpose (fp16, layer-batched) ======================
__global__ void conv_wt_kernel(const float* __restrict__ W,
                               __half* __restrict__ Th, int K, int N,
                               size_t in_stride, size_t out_stride)
{
    W  += (size_t)blockIdx.z * in_stride;
    Th += (size_t)blockIdx.z * out_stride;
    __shared__ float s[32][33];
    int tx = threadIdx.x, ty = threadIdx.y;   // 32 x 8
    int n0 = blockIdx.x * 32, k0 = blockIdx.y * 32;
    #pragma unroll
    for (int j = 0; j < 32; j += 8)
        s[ty + j][tx] = W[(size_t)(k0 + ty + j) * N + n0 + tx];
    __syncthreads();
    #pragma unroll
    for (int j = 0; j < 32; j += 8) {
        int n = n0 + ty + j, k = k0 + tx;
        Th[(size_t)n * K + k] = __float2half_rn(s[tx][ty + j]);
    }
}

// ====================== fp16 HMMA GEMM (K-chunk 64, 2-stage) ======================
#define TILE_B   18432   // 128 rows x 144 B
#define STAGE_B  36864   // A + B
#define GSMEM    73728   // 2 stages
#define STRIDE   72      // elements per smem row (144 B)

// flags: 1 = relu, 2 = write fp32 C, 4 = write fp16 (Oh), 8 = qkv col-scale, 32 = add X residual
__global__ __launch_bounds__(256, 2)
void gemm_hmma(const __half* __restrict__ Ah, const __half* __restrict__ Bh,
               const float* __restrict__ bias, float* __restrict__ C,
               __half* __restrict__ Oh, const float* __restrict__ X,
               int M, int N, int K, int flags, float oscale)
{
    extern __shared__ char sm[];
    uint32_t sb = smem_u32(sm);
    int tid = threadIdx.x, lane = tid & 31, wid = tid >> 5;
    int wm = wid & 1, wn = wid >> 1;
    int m0 = blockIdx.y * 128, n0 = blockIdx.x * 128;

    // loading: idx 0..1023 -> r = idx>>3 (0..127), c = idx&7 (16B segs of 128B row)
    int lrow = tid >> 1, lseg8 = (tid & 1) * 4;   // each thread: rows tid>>1, segs lseg8..lseg8+3
    const char* gA = (const char*)(Ah + (size_t)(m0 + lrow) * K) + lseg8 * 16;
    const char* gB = (const char*)(Bh + (size_t)(n0 + lrow) * K) + lseg8 * 16;
    uint32_t soff = (uint32_t)(lrow * 144 + lseg8 * 16);

    float acc[4][4][4];
    #pragma unroll
    for (int a = 0; a < 4; a++)
        #pragma unroll
        for (int b = 0; b < 4; b++)
            #pragma unroll
            for (int c = 0; c < 4; c++) acc[a][b][c] = 0.f;

    int NC = K >> 6;    // K-chunk = 64

#define LOADC(cc, st) do { \
    size_t ko = (size_t)(cc) * 128; /* 64 fp16 = 128 B */ \
    uint32_t s0 = sb + (st) * STAGE_B + soff; \
    cp16(s0,               gA + ko);      cp16(s0 + 16,          gA + ko + 16); \
    cp16(s0 + 32,          gA + ko + 32); cp16(s0 + 48,          gA + ko + 48); \
    cp16(s0 + TILE_B,      gB + ko);      cp16(s0 + TILE_B + 16, gB + ko + 16); \
    cp16(s0 + TILE_B + 32, gB + ko + 32); cp16(s0 + TILE_B + 48, gB + ko + 48); \
    asm volatile("cp.async.commit_group;"); \
} while (0)

    LOADC(0, 0);

    int ar = lane & 15, a8 = lane >> 4;

    for (int c = 0; c < NC; c++) {
        int st = c & 1;
        if (c + 1 < NC) {
            LOADC(c + 1, st ^ 1);
            asm volatile("cp.async.wait_group 1;");
        } else {
            asm volatile("cp.async.wait_group 0;");
        }
        __syncthreads();

        uint32_t tb = sb + st * STAGE_B;
        #pragma unroll
        for (int ks = 0; ks < 4; ks++) {
            int acol = ks * 16 + a8 * 8;
            uint32_t Ahf[4][4], Bhf[4][2];
            #pragma unroll
            for (int mt = 0; mt < 4; mt++) {
                uint32_t ad = tb + (uint32_t)((wm * 64 + mt * 16 + ar) * STRIDE + acol) * 2;
                ldsm4(Ahf[mt], ad);
            }
            #pragma unroll
            for (int p = 0; p < 2; p++) {
                uint32_t bd = tb + TILE_B +
                              (uint32_t)((wn * 32 + p * 16 + ar) * STRIDE + acol) * 2;
                uint32_t t[4];
                ldsm4(t, bd);
                Bhf[2*p][0] = t[0]; Bhf[2*p][1] = t[2];
                Bhf[2*p+1][0] = t[1]; Bhf[2*p+1][1] = t[3];
            }
            #pragma unroll
            for (int mt = 0; mt < 4; mt++)
                #pragma unroll
                for (int nt = 0; nt < 4; nt++)
                    mma16816h(acc[mt][nt], Ahf[mt], Bhf[nt]);
        }
        __syncthreads();
    }
#undef LOADC

    int relu = flags & 1, wf = flags & 2, wh = flags & 4, addx = flags & 32;
    int r_base = m0 + wm * 64 + (lane >> 2);
    int c_base = n0 + wn * 32 + (lane & 3) * 2;
    #pragma unroll
    for (int nt = 0; nt < 4; nt++) {
        int c0 = c_base + nt * 8;
        float sc = (flags & 8) ? ((c0 < 512) ? 0.125f : 1.0f) : oscale;
        float2 bv = *(const float2*)(bias + c0);
        #pragma unroll
        for (int mt = 0; mt < 4; mt++) {
            #pragma unroll
            for (int h = 0; h < 2; h++) {
                int r = r_base + mt * 16 + h * 8;
                size_t off = (size_t)r * N + c0;
                float v0 = (acc[mt][nt][h*2+0] + bv.x) * sc;
                float v1 = (acc[mt][nt][h*2+1] + bv.y) * sc;
                if (relu) { v0 = fmaxf(v0, 0.f); v1 = fmaxf(v1, 0.f); }
                if (addx) {
                    float2 xv = *(const float2*)(X + off);
                    v0 += xv.x; v1 += xv.y;
                }
                if (wf) *(float2*)(C + off) = make_float2(v0, v1);
                if (wh) store_f16x2(Oh, off, v0, v1);
            }
        }
    }
}

// ====================== fp16 HMMA flash attention (single-term) ======================
#define AQ_OFF    0
#define ASTG_BASE 18432
#define AK_OFF    0
#define AV_OFF    9216
#define ABK_OFF   18432
#define ASTG_SZ   26624
#define ATB_OFF   (ASTG_BASE + 2*ASTG_SZ)        // 71680
#define ATTN2_SMEM (ATB_OFF + 128)               // 71808

__device__ __forceinline__ void load_kv_tile(
    uint32_t sb, const __half* qv, const unsigned char* bkp,
    int b, int h, int q0, int kt, int st, int tid)
{
    uint32_t stb = sb + ASTG_BASE + st * ASTG_SZ;
    const char* gk = (const char*)qv + ((size_t)(b * L_) * NQKV + 512  + h * DH_) * 2;
    const char* gv = (const char*)qv + ((size_t)(b * L_) * NQKV + 1024 + h * DH_) * 2;
    #pragma unroll
    for (int i = 0; i < 2; i++) {
        int idx = tid + i * 256;
        int r = idx >> 3, c = idx & 7;
        size_t go = (size_t)(kt * 64 + r) * (NQKV * 2) + c * 16;
        uint32_t so = (uint32_t)(r * 144 + c * 16);
        cp16(stb + AK_OFF + so, gk + go);
        cp16(stb + AV_OFF + so, gv + go);
    }
    #pragma unroll
    for (int i = 0; i < 2; i++) {
        int idx = tid + i * 256;
        int r = idx >> 2, c = idx & 3;
        size_t go = ((size_t)(b * L_ + q0 + r)) * L_ + kt * 64 + c * 16;
        cp16(stb + ABK_OFF + (uint32_t)(r * 64 + c * 16), bkp + go);
    }
    asm volatile("cp.async.commit_group;");
}

__global__ __launch_bounds__(256, 2)
void attn_mma(const __half* __restrict__ qv,
              const unsigned char* __restrict__ bkp, const float* __restrict__ tbias,
              __half* __restrict__ oh)
{
    extern __shared__ char sm[];
    uint32_t sb = smem_u32(sm);
    float* smf = (float*)sm;

    int qt = blockIdx.x, h = blockIdx.y, b = blockIdx.z;
    int q0 = qt * 128;
    int tid = threadIdx.x, lane = tid & 31, wid = tid >> 5;
    int g = lane >> 2, tig = lane & 3, tig2 = tig * 2;
    int ar = lane & 15, a8 = lane >> 4;

    {
        const char* gq = (const char*)qv + ((size_t)(b * L_ + q0) * NQKV + h * DH_) * 2;
        #pragma unroll
        for (int i = 0; i < 4; i++) {
            int idx = tid + i * 256;
            int r = idx >> 3, c = idx & 7;
            cp16(sb + AQ_OFF + (uint32_t)(r * 144 + c * 16),
                 gq + (size_t)r * (NQKV * 2) + c * 16);
        }
    }
    if (tid < NB_) smf[ATB_OFF/4 + tid] = tbias[tid * H_ + h];

    int nkt = 2 * qt + 2;
    load_kv_tile(sb, qv, bkp, b, h, q0, 0, 0, tid);

    int qg0 = q0 + wid * 16 + g, qg1 = qg0 + 8;
    int r0l = wid * 16 + g, r1l = r0l + 8;
    float m0 = -1e30f, m1 = -1e30f, l0 = 0.f, l1 = 0.f;
    float acc_o[8][4];
    #pragma unroll
    for (int nt = 0; nt < 8; nt++)
        #pragma unroll
        for (int i = 0; i < 4; i++) acc_o[nt][i] = 0.f;

    uint32_t qhf[4][4];
    asm volatile("cp.async.wait_group 0;");
    __syncthreads();
    #pragma unroll
    for (int kc = 0; kc < 4; kc++) {
        uint32_t ad = sb + AQ_OFF + (uint32_t)((wid * 16 + ar) * 72 + kc * 16 + a8 * 8) * 2;
        ldsm4(qhf[kc], ad);
    }

    const float* tb = (const float*)(sm + ATB_OFF);

    for (int kt = 0; kt < nkt; kt++) {
        int st = kt & 1;
        if (kt + 1 < nkt) {
            load_kv_tile(sb, qv, bkp, b, h, q0, kt + 1, st ^ 1, tid);
            asm volatile("cp.async.wait_group 1;");
        } else {
            asm volatile("cp.async.wait_group 0;");
        }
        __syncthreads();

        uint32_t stb = sb + ASTG_BASE + st * ASTG_SZ;
        const unsigned char* bkt = (const unsigned char*)(sm + ASTG_BASE + st * ASTG_SZ + ABK_OFF);

        float S[8][4];
        #pragma unroll
        for (int nt = 0; nt < 8; nt++)
            #pragma unroll
            for (int i = 0; i < 4; i++) S[nt][i] = 0.f;

        #pragma unroll
        for (int kc = 0; kc < 4; kc++) {
            #pragma unroll
            for (int nt2 = 0; nt2 < 4; nt2++) {
                uint32_t kd = stb + AK_OFF + (uint32_t)((nt2 * 16 + ar) * 72 + kc * 16 + a8 * 8) * 2;
                uint32_t th[4];
                ldsm4(th, kd);
                uint32_t b0[2] = {th[0], th[2]}, b1[2] = {th[1], th[3]};
                mma16816h(S[2*nt2],   qhf[kc], b0);
                mma16816h(S[2*nt2+1], qhf[kc], b1);
            }
        }

        bool needMask = (kt >= 2 * qt);
        float mx0 = -1e30f, mx1 = -1e30f;
        #pragma unroll
        for (int nt = 0; nt < 8; nt++) {
            int colb = nt * 8 + tig2;
            uint32_t pb0 = *(const unsigned short*)(bkt + r0l * 64 + colb);
            uint32_t pb1 = *(const unsigned short*)(bkt + r1l * 64 + colb);
            float s0a = S[nt][0] + tb[pb0 & 0xFF];
            float s0b = S[nt][1] + tb[pb0 >> 8];
            float s1a = S[nt][2] + tb[pb1 & 0xFF];
            float s1b = S[nt][3] + tb[pb1 >> 8];
            if (needMask) {
                int kg = kt * 64 + colb;
                if (kg     > qg0) s0a = -1e30f;
                if (kg + 1 > qg0) s0b = -1e30f;
                if (kg     > qg1) s1a = -1e30f;
                if (kg + 1 > qg1) s1b = -1e30f;
            }
            S[nt][0] = s0a; S[nt][1] = s0b; S[nt][2] = s1a; S[nt][3] = s1b;
            mx0 = fmaxf(mx0, fmaxf(s0a, s0b));
            mx1 = fmaxf(mx1, fmaxf(s1a, s1b));
        }
        mx0 = fmaxf(mx0, __shfl_xor_sync(~0u, mx0, 1));
        mx0 = fmaxf(mx0, __shfl_xor_sync(~0u, mx0, 2));
        mx1 = fmaxf(mx1, __shfl_xor_sync(~0u, mx1, 1));
        mx1 = fmaxf(mx1, __shfl_xor_sync(~0u, mx1, 2));
        float mn0 = fmaxf(m0, mx0), mn1 = fmaxf(m1, mx1);
        float rs0 = __expf(m0 - mn0), rs1 = __expf(m1 - mn1);
        m0 = mn0; m1 = mn1;

        float sum0 = 0.f, sum1 = 0.f;
        #pragma unroll
        for (int nt = 0; nt < 8; nt++) {
            float p0 = __expf(S[nt][0] - mn0);
            float p1 = __expf(S[nt][1] - mn0);
            float p2 = __expf(S[nt][2] - mn1);
            float p3 = __expf(S[nt][3] - mn1);
            S[nt][0] = p0; S[nt][1] = p1; S[nt][2] = p2; S[nt][3] = p3;
            sum0 += p0 + p1; sum1 += p2 + p3;
        }
        sum0 += __shfl_xor_sync(~0u, sum0, 1); sum0 += __shfl_xor_sync(~0u, sum0, 2);
        sum1 += __shfl_xor_sync(~0u, sum1, 1); sum1 += __shfl_xor_sync(~0u, sum1, 2);
        l0 = l0 * rs0 + sum0;
        l1 = l1 * rs1 + sum1;
        #pragma unroll
        for (int nt = 0; nt < 8; nt++) {
            acc_o[nt][0] *= rs0; acc_o[nt][1] *= rs0;
            acc_o[nt][2] *= rs1; acc_o[nt][3] *= rs1;
        }

        #pragma unroll
        for (int t = 0; t < 4; t++) {
            uint32_t ap[4];
            ap[0] = pack_f16(S[2*t][0],   S[2*t][1]);
            ap[1] = pack_f16(S[2*t][2],   S[2*t][3]);
            ap[2] = pack_f16(S[2*t+1][0], S[2*t+1][1]);
            ap[3] = pack_f16(S[2*t+1][2], S[2*t+1][3]);
            #pragma unroll
            for (int j2 = 0; j2 < 4; j2++) {
                uint32_t vd = stb + AV_OFF + (uint32_t)((t * 16 + ar) * 72 + j2 * 16 + a8 * 8) * 2;
                uint32_t th[4];
                ldsm4t(th, vd);
                uint32_t b0[2] = {th[0], th[1]}, b1[2] = {th[2], th[3]};
                mma16816h(acc_o[2*j2],   ap, b0);
                mma16816h(acc_o[2*j2+1], ap, b1);
            }
        }
        __syncthreads();
    }

    float inv0 = 1.0f / l0, inv1 = 1.0f / l1;
    size_t row0 = ((size_t)(b * L_ + qg0)) * D_ + h * DH_;
    size_t row1 = ((size_t)(b * L_ + qg1)) * D_ + h * DH_;
    #pragma unroll
    for (int nt = 0; nt < 8; nt++) {
        int cc = nt * 8 + tig2;
        store_f16x2(oh, row0 + cc, acc_o[nt][0] * inv0, acc_o[nt][1] * inv0);
        store_f16x2(oh, row1 + cc, acc_o[nt][2] * inv1, acc_o[nt][3] * inv1);
    }
}

// ====================== pure LayerNorm (input already has residual) ======================
__global__ __launch_bounds__(128)
void ln_kernel(const float* __restrict__ xin,
               const float* __restrict__ g, const float* __restrict__ bb,
               float* __restrict__ xout, __half* __restrict__ oh, int writeH)
{
    __shared__ float sy[D_];
    __shared__ float red[4];
    int row = blockIdx.x;
    int tid = threadIdx.x;
    int lane = tid & 31, w = tid >> 5;

    const float* xr = xin + (size_t)row * D_;

    float lsum = 0.f;
    #pragma unroll
    for (int i = 0; i < 4; i++) {
        int d = tid + i * 128;
        float val = xr[d];
        sy[d] = val;
        lsum += val;
    }
    #pragma unroll
    for (int o = 16; o > 0; o >>= 1) lsum += __shfl_xor_sync(~0u, lsum, o);
    if (lane == 0) red[w] = lsum;
    __syncthreads();
    float mean = (red[0] + red[1] + red[2] + red[3]) * (1.0f / D_);
    __syncthreads();

    float lv = 0.f;
    #pragma unroll
    for (int i = 0; i < 4; i++) {
        int d = tid + i * 128;
        float c = sy[d] - mean;
        lv += c * c;
    }
    #pragma unroll
    for (int o = 16; o > 0; o >>= 1) lv += __shfl_xor_sync(~0u, lv, o);
    if (lane == 0) red[w] = lv;
    __syncthreads();
    float var = (red[0] + red[1] + red[2] + red[3]) * (1.0f / D_);
    float inv = rsqrtf(var + 1e-5f);

    #pragma unroll
    for (int i = 0; i < 4; i++) {
        int d = tid + i * 128;
        float val = (sy[d] - mean) * inv * g[d] + bb[d];
        xout[(size_t)row * D_ + d] = val;
        if (writeH)
            oh[(size_t)row * D_ + d] = __float2half_rn(val);
    }
}

// ====================== launch ======================
extern "C" void kernel_launch(void* const* d_in, const int* in_sizes, int n_in,
                              void* d_out, int out_size)
{
    const int*   seq      = (const int*)  d_in[0];
    const float* ts       = (const float*)d_in[1];
    const float* item_emb = (const float*)d_in[2];
    const float* pos_emb  = (const float*)d_in[3];
    const float* Wq  = (const float*)d_in[4];  const float* bq  = (const float*)d_in[5];
    const float* Wk  = (const float*)d_in[6];  const float* bk  = (const float*)d_in[7];
    const float* Wv  = (const float*)d_in[8];  const float* bv  = (const float*)d_in[9];
    const float* tbias = (const float*)d_in[10];
    const float* Wo  = (const float*)d_in[11]; const float* bo  = (const float*)d_in[12];
    const float* g1  = (const float*)d_in[13]; const float* be1 = (const float*)d_in[14];
    const float* W1  = (const float*)d_in[15]; const float* bf1 = (const float*)d_in[16];
    const float* W2  = (const float*)d_in[17]; const float* bf2 = (const float*)d_in[18];
    const float* g2  = (const float*)d_in[19]; const float* be2 = (const float*)d_in[20];

    float *x, *po, *bqkv;
    __half *ah, *fh, *qv, *wth;
    unsigned char* bkptr;
    cudaGetSymbolAddress((void**)&x,  g_x);
    cudaGetSymbolAddress((void**)&po, g_po);
    cudaGetSymbolAddress((void**)&ah, g_ah);
    cudaGetSymbolAddress((void**)&qv, g_qv);
    cudaGetSymbolAddress((void**)&fh, g_fh);
    cudaGetSymbolAddress((void**)&wth, g_wth);
    cudaGetSymbolAddress((void**)&bkptr, g_bk);
    cudaGetSymbolAddress((void**)&bqkv, g_bqkv);

    cudaFuncSetAttribute(attn_mma,  cudaFuncAttributeMaxDynamicSharedMemorySize, ATTN2_SMEM);
    cudaFuncSetAttribute(gemm_hmma, cudaFuncAttributeMaxDynamicSharedMemorySize, GSMEM);

    const size_t OQ = 0, OO = 786432, O1 = 1048576, O2 = 2097152;
    dim3 t32(32, 8);
    dim3 gQKV(NQKV / 128, ML_ / 128);  // (12, 128)
    dim3 gD(D_ / 128, ML_ / 128);      // (4, 128)
    dim3 gF(DFF_ / 128, ML_ / 128);    // (16, 128)
    dim3 ga(L_ / 128, H_, B_);         // (4, 8, 32)

    conv_wt_kernel<<<dim3(16, 16, NL_), t32>>>(Wq, wth+0,      512, 512,  (size_t)D_*D_,   WT_LAYER);
    conv_wt_kernel<<<dim3(16, 16, NL_), t32>>>(Wk, wth+262144, 512, 512,  (size_t)D_*D_,   WT_LAYER);
    conv_wt_kernel<<<dim3(16, 16, NL_), t32>>>(Wv, wth+524288, 512, 512,  (size_t)D_*D_,   WT_LAYER);
    conv_wt_kernel<<<dim3(16, 16, NL_), t32>>>(Wo, wth+OO,     512, 512,  (size_t)D_*D_,   WT_LAYER);
    conv_wt_kernel<<<dim3(64, 16, NL_), t32>>>(W1, wth+O1,     512, 2048, (size_t)D_*DFF_, WT_LAYER);
    conv_wt_kernel<<<dim3(16, 64, NL_), t32>>>(W2, wth+O2,     2048, 512, (size_t)DFF_*D_, WT_LAYER);

    biascat_kernel<<<(NL_*NQKV)/256, 256>>>(bq, bk, bv);
    embed_kernel<<<(ML_ * D_ / 4) / 256, 256>>>(seq, item_emb, pos_emb);
    bucket_kernel<<<(B_*L_*L_)/256, 256>>>(ts);

    for (int i = 0; i < NL_; i++) {
        size_t wb = (size_t)i * WT_LAYER;

        // fused QKV -> fp16 packed output, q-section scaled 0.125
        gemm_hmma<<<gQKV, 256, GSMEM>>>(ah, wth+wb+OQ, bqkv + i*NQKV,
                                        0, qv, 0, ML_, NQKV, D_, 4|8, 1.0f);

        attn_mma<<<ga, 256, ATTN2_SMEM>>>(qv, bkptr, tbias + (size_t)i*NB_*H_, ah);

        // Wo GEMM with fused residual add (po = WoOut + bias + x)
        gemm_hmma<<<gD, 256, GSMEM>>>(ah, wth+wb+OO, bo + i*D_, po, 0, x, ML_, D_, D_, 2|32, 1.0f);
        ln_kernel<<<ML_, 128>>>(po, g1 + i*D_, be1 + i*D_, x, ah, 1);

        gemm_hmma<<<gF, 256, GSMEM>>>(ah, wth+wb+O1, bf1 + i*DFF_, 0, fh, 0, ML_, DFF_, D_, 1|4, 1.0f);
        // FF2 GEMM with fused residual add (po = FF2Out + bias + x)
        gemm_hmma<<<gD, 256, GSMEM>>>(fh, wth+wb+O2, bf2 + i*D_, po, 0, x, ML_, D_, DFF_, 2|32, 1.0f);

        float* xo = (i == NL_ - 1) ? (float*)d_out : x;
        ln_kernel<<<ML_, 128>>>(po, g2 + i*D_, be2 + i*D_, xo, ah, (i < NL_ - 1) ? 1 : 0);
    }
}

// round 13
// speedup vs baseline: 1.1608x; 1.1608x over previous
#include <cuda_runtime.h>
#include <cuda_fp16.h>
#include <math.h>
#include <stdint.h>

#define B_   32
#define L_   512
#define D_   512
#define H_   8
#define DH_  64
#define NL_  2
#define DFF_ 2048
#define NB_  32
#define ML_  (B_*L_)   // 16384 rows
#define NQKV 1536

// ---------------- scratch (device globals; no allocations) ----------------
__device__ float g_x [ML_*D_];
__device__ float g_po[ML_*D_];
__device__ __align__(16) __half g_ah[ML_*D_];
__device__ __align__(16) __half g_fh[ML_*DFF_];
__device__ __align__(16) __half g_qv[ML_*NQKV];
#define WT_LAYER (4*512*512 + 2048*512 + 512*2048)
__device__ __align__(16) __half g_wth[NL_*WT_LAYER];
__device__ __align__(16) unsigned char g_bk[B_*L_*L_];
__device__ float g_bqkv[NL_*NQKV];

// ====================== PTX helpers ======================
__device__ __forceinline__ uint32_t smem_u32(const void* p) {
    uint32_t a;
    asm("{ .reg .u64 t; cvta.to.shared.u64 t, %1; cvt.u32.u64 %0, t; }" : "=r"(a) : "l"(p));
    return a;
}
__device__ __forceinline__ void cp16(uint32_t s, const void* g) {
    asm volatile("cp.async.cg.shared.global [%0], [%1], 16;" :: "r"(s), "l"(g));
}
__device__ __forceinline__ void ldsm4(uint32_t* r, uint32_t a) {
    asm volatile("ldmatrix.sync.aligned.m8n8.x4.shared.b16 {%0,%1,%2,%3}, [%4];"
        : "=r"(r[0]), "=r"(r[1]), "=r"(r[2]), "=r"(r[3]) : "r"(a));
}
__device__ __forceinline__ void ldsm4t(uint32_t* r, uint32_t a) {
    asm volatile("ldmatrix.sync.aligned.m8n8.x4.trans.shared.b16 {%0,%1,%2,%3}, [%4];"
        : "=r"(r[0]), "=r"(r[1]), "=r"(r[2]), "=r"(r[3]) : "r"(a));
}
__device__ __forceinline__ void mma16816h(float* c, const uint32_t* a, const uint32_t* b) {
    asm volatile("mma.sync.aligned.m16n8k16.row.col.f32.f16.f16.f32 "
        "{%0,%1,%2,%3}, {%4,%5,%6,%7}, {%8,%9}, {%0,%1,%2,%3};"
        : "+f"(c[0]), "+f"(c[1]), "+f"(c[2]), "+f"(c[3])
        : "r"(a[0]), "r"(a[1]), "r"(a[2]), "r"(a[3]), "r"(b[0]), "r"(b[1]));
}
__device__ __forceinline__ uint32_t pack_f16(float x, float y) {
    __half2 t = __halves2half2(__float2half_rn(x), __float2half_rn(y));
    return *(uint32_t*)&t;
}
__device__ __forceinline__ void store_f16x2(__half* O, size_t off, float v0, float v1) {
    *(uint32_t*)(O + off) = pack_f16(v0, v1);
}

// ====================== time bucket ======================
__device__ __forceinline__ int time_bucket(float delta)
{
    float a = fmaxf(fabsf(delta), 1.0f);
    const float scale = 0.71018780958489f;   // float32(log2(2592000)/30)
    int idx = (int)(log2f(a) / scale) + 1;
    idx = max(1, min(idx, NB_ - 2));
    if (a <= 1.0f)       idx = 0;
    if (a >= 2592000.0f) idx = NB_ - 1;
    return idx;
}

__global__ void bucket_kernel(const float* __restrict__ ts)
{
    int idx = blockIdx.x * blockDim.x + threadIdx.x;   // over B*L*L
    int k = idx & (L_-1);
    int q = (idx >> 9) & (L_-1);
    int b = idx >> 18;
    float d = ts[b * L_ + q] - ts[b * L_ + k];
    g_bk[idx] = (unsigned char)time_bucket(d);
}

__global__ void biascat_kernel(const float* __restrict__ bq,
                               const float* __restrict__ bk,
                               const float* __restrict__ bv)
{
    int i = blockIdx.x * blockDim.x + threadIdx.x;   // NL*1536
    int l = i / NQKV, c = i % NQKV;
    float v = (c < 512) ? bq[l*512 + c] : (c < 1024 ? bk[l*512 + c - 512] : bv[l*512 + c - 1024]);
    g_bqkv[i] = v;
}

// ====================== embedding (+ fp16) ======================
__global__ void embed_kernel(const int* __restrict__ seq,
                             const float* __restrict__ item_emb,
                             const float* __restrict__ pos_emb)
{
    int idx = blockIdx.x * blockDim.x + threadIdx.x;   // over ML*D/4
    int d4 = idx & (D_/4 - 1);
    int bl = idx >> 7;
    int l  = bl & (L_-1);
    int it = seq[bl];
    float4 a = *(const float4*)(item_emb + (size_t)it * D_ + d4*4);
    float4 p = *(const float4*)(pos_emb  + (size_t)l  * D_ + d4*4);
    a.x += p.x; a.y += p.y; a.z += p.z; a.w += p.w;
    ((float4*)g_x)[idx] = a;
    size_t off = (size_t)idx * 4;
    store_f16x2(g_ah, off,     a.x, a.y);
    store_f16x2(g_ah, off + 2, a.z, a.w);
}

// ====================== weight transpose (fp16, layer-batched) ======================
__global__ void conv_wt_kernel(const float* __restrict__ W,
                               __half* __restrict__ Th, int K, int N,
                               size_t in_stride, size_t out_stride)
{
    W  += (size_t)blockIdx.z * in_stride;
    Th += (size_t)blockIdx.z * out_stride;
    __shared__ float s[32][33];
    int tx = threadIdx.x, ty = threadIdx.y;   // 32 x 8
    int n0 = blockIdx.x * 32, k0 = blockIdx.y * 32;
    #pragma unroll
    for (int j = 0; j < 32; j += 8)
        s[ty + j][tx] = W[(size_t)(k0 + ty + j) * N + n0 + tx];
    __syncthreads();
    #pragma unroll
    for (int j = 0; j < 32; j += 8) {
        int n = n0 + ty + j, k = k0 + tx;
        Th[(size_t)n * K + k] = __float2half_rn(s[tx][ty + j]);
    }
}

// ====================== fp16 HMMA GEMM (K-chunk 32, 3-stage; R11 mainloop) ======================
#define TILE_B   10240
#define STAGE_B  20480   // 2 tiles (A, B)
#define GSMEM    61440   // 3 stages
#define STRIDE   40

// flags: 1 = relu, 2 = write fp32 C, 4 = write fp16 (Oh), 8 = qkv col-scale, 32 = add X residual
__global__ __launch_bounds__(256, 2)
void gemm_hmma(const __half* __restrict__ Ah, const __half* __restrict__ Bh,
               const float* __restrict__ bias, float* __restrict__ C,
               __half* __restrict__ Oh, const float* __restrict__ X,
               int M, int N, int K, int flags, float oscale)
{
    extern __shared__ char sm[];
    uint32_t sb = smem_u32(sm);
    int tid = threadIdx.x, lane = tid & 31, wid = tid >> 5;
    int wm = wid & 1, wn = wid >> 1;
    int m0 = blockIdx.y * 128, n0 = blockIdx.x * 128;

    int lrow = tid >> 2, lseg = tid & 3;
    const char* gAh = (const char*)(Ah + (size_t)(m0 + lrow) * K + lseg * 8);
    const char* gBh = (const char*)(Bh + (size_t)(n0 + lrow) * K + lseg * 8);
    size_t rowskip = (size_t)64 * K * 2;
    uint32_t s0off = (uint32_t)(lrow * STRIDE + lseg * 8) * 2;
    uint32_t s1off = s0off + 64 * STRIDE * 2;

    float acc[4][4][4];
    #pragma unroll
    for (int a = 0; a < 4; a++)
        #pragma unroll
        for (int b = 0; b < 4; b++)
            #pragma unroll
            for (int c = 0; c < 4; c++) acc[a][b][c] = 0.f;

    int NC = K >> 5;

#define LOADC(cc, st) do { \
    size_t ko = (size_t)(cc) * 64; \
    uint32_t s0 = sb + (st) * STAGE_B + s0off; \
    uint32_t s1 = sb + (st) * STAGE_B + s1off; \
    cp16(s0,          gAh + ko); cp16(s1,          gAh + ko + rowskip); \
    cp16(s0 + TILE_B, gBh + ko); cp16(s1 + TILE_B, gBh + ko + rowskip); \
    asm volatile("cp.async.commit_group;"); \
} while (0)

    LOADC(0, 0);
    LOADC(1, 1);

    int ar = lane & 15, a8 = lane >> 4;
    int st = 0;

    for (int c = 0; c < NC; c++) {
        if (c + 2 < NC) {
            LOADC(c + 2, (c + 2) % 3);
            asm volatile("cp.async.wait_group 2;");
        } else if (c + 1 < NC) {
            asm volatile("cp.async.wait_group 1;");
        } else {
            asm volatile("cp.async.wait_group 0;");
        }
        __syncthreads();

        uint32_t tb = sb + st * STAGE_B;
        st = (st + 1 == 3) ? 0 : st + 1;
        #pragma unroll
        for (int ks = 0; ks < 2; ks++) {
            int acol = ks * 16 + a8 * 8;
            uint32_t Ahf[4][4], Bhf[4][2];
            #pragma unroll
            for (int mt = 0; mt < 4; mt++) {
                uint32_t ad = tb + (uint32_t)((wm * 64 + mt * 16 + ar) * STRIDE + acol) * 2;
                ldsm4(Ahf[mt], ad);
            }
            #pragma unroll
            for (int p = 0; p < 2; p++) {
                uint32_t bd = tb + TILE_B +
                              (uint32_t)((wn * 32 + p * 16 + ar) * STRIDE + acol) * 2;
                uint32_t t[4];
                ldsm4(t, bd);
                Bhf[2*p][0] = t[0]; Bhf[2*p][1] = t[2];
                Bhf[2*p+1][0] = t[1]; Bhf[2*p+1][1] = t[3];
            }
            #pragma unroll
            for (int mt = 0; mt < 4; mt++)
                #pragma unroll
                for (int nt = 0; nt < 4; nt++)
                    mma16816h(acc[mt][nt], Ahf[mt], Bhf[nt]);
        }
        __syncthreads();
    }
#undef LOADC

    int relu = flags & 1, wf = flags & 2, wh = flags & 4, addx = flags & 32;
    int r_base = m0 + wm * 64 + (lane >> 2);
    int c_base = n0 + wn * 32 + (lane & 3) * 2;
    #pragma unroll
    for (int nt = 0; nt < 4; nt++) {
        int c0 = c_base + nt * 8;
        float sc = (flags & 8) ? ((c0 < 512) ? 0.125f : 1.0f) : oscale;
        float2 bv = *(const float2*)(bias + c0);
        #pragma unroll
        for (int mt = 0; mt < 4; mt++) {
            #pragma unroll
            for (int h = 0; h < 2; h++) {
                int r = r_base + mt * 16 + h * 8;
                size_t off = (size_t)r * N + c0;
                float v0 = (acc[mt][nt][h*2+0] + bv.x) * sc;
                float v1 = (acc[mt][nt][h*2+1] + bv.y) * sc;
                if (relu) { v0 = fmaxf(v0, 0.f); v1 = fmaxf(v1, 0.f); }
                if (addx) {
                    float2 xv = *(const float2*)(X + off);
                    v0 += xv.x; v1 += xv.y;
                }
                if (wf) *(float2*)(C + off) = make_float2(v0, v1);
                if (wh) store_f16x2(Oh, off, v0, v1);
            }
        }
    }
}

// ====================== fp16 HMMA flash attention (single-term) ======================
#define AQ_OFF    0
#define ASTG_BASE 18432
#define AK_OFF    0
#define AV_OFF    9216
#define ABK_OFF   18432
#define ASTG_SZ   26624
#define ATB_OFF   (ASTG_BASE + 2*ASTG_SZ)        // 71680
#define ATTN2_SMEM (ATB_OFF + 128)               // 71808

__device__ __forceinline__ void load_kv_tile(
    uint32_t sb, const __half* qv, const unsigned char* bkp,
    int b, int h, int q0, int kt, int st, int tid)
{
    uint32_t stb = sb + ASTG_BASE + st * ASTG_SZ;
    const char* gk = (const char*)qv + ((size_t)(b * L_) * NQKV + 512  + h * DH_) * 2;
    const char* gv = (const char*)qv + ((size_t)(b * L_) * NQKV + 1024 + h * DH_) * 2;
    #pragma unroll
    for (int i = 0; i < 2; i++) {
        int idx = tid + i * 256;
        int r = idx >> 3, c = idx & 7;
        size_t go = (size_t)(kt * 64 + r) * (NQKV * 2) + c * 16;
        uint32_t so = (uint32_t)(r * 144 + c * 16);
        cp16(stb + AK_OFF + so, gk + go);
        cp16(stb + AV_OFF + so, gv + go);
    }
    #pragma unroll
    for (int i = 0; i < 2; i++) {
        int idx = tid + i * 256;
        int r = idx >> 2, c = idx & 3;
        size_t go = ((size_t)(b * L_ + q0 + r)) * L_ + kt * 64 + c * 16;
        cp16(stb + ABK_OFF + (uint32_t)(r * 64 + c * 16), bkp + go);
    }
    asm volatile("cp.async.commit_group;");
}

__global__ __launch_bounds__(256, 2)
void attn_mma(const __half* __restrict__ qv,
              const unsigned char* __restrict__ bkp, const float* __restrict__ tbias,
              __half* __restrict__ oh)
{
    extern __shared__ char sm[];
    uint32_t sb = smem_u32(sm);
    float* smf = (float*)sm;

    int qt = blockIdx.x, h = blockIdx.y, b = blockIdx.z;
    int q0 = qt * 128;
    int tid = threadIdx.x, lane = tid & 31, wid = tid >> 5;
    int g = lane >> 2, tig = lane & 3, tig2 = tig * 2;
    int ar = lane & 15, a8 = lane >> 4;

    {
        const char* gq = (const char*)qv + ((size_t)(b * L_ + q0) * NQKV + h * DH_) * 2;
        #pragma unroll
        for (int i = 0; i < 4; i++) {
            int idx = tid + i * 256;
            int r = idx >> 3, c = idx & 7;
            cp16(sb + AQ_OFF + (uint32_t)(r * 144 + c * 16),
                 gq + (size_t)r * (NQKV * 2) + c * 16);
        }
    }
    if (tid < NB_) smf[ATB_OFF/4 + tid] = tbias[tid * H_ + h];

    int nkt = 2 * qt + 2;
    load_kv_tile(sb, qv, bkp, b, h, q0, 0, 0, tid);

    int qg0 = q0 + wid * 16 + g, qg1 = qg0 + 8;
    int r0l = wid * 16 + g, r1l = r0l + 8;
    float m0 = -1e30f, m1 = -1e30f, l0 = 0.f, l1 = 0.f;
    float acc_o[8][4];
    #pragma unroll
    for (int nt = 0; nt < 8; nt++)
        #pragma unroll
        for (int i = 0; i < 4; i++) acc_o[nt][i] = 0.f;

    uint32_t qhf[4][4];
    asm volatile("cp.async.wait_group 0;");
    __syncthreads();
    #pragma unroll
    for (int kc = 0; kc < 4; kc++) {
        uint32_t ad = sb + AQ_OFF + (uint32_t)((wid * 16 + ar) * 72 + kc * 16 + a8 * 8) * 2;
        ldsm4(qhf[kc], ad);
    }

    const float* tb = (const float*)(sm + ATB_OFF);

    for (int kt = 0; kt < nkt; kt++) {
        int st = kt & 1;
        if (kt + 1 < nkt) {
            load_kv_tile(sb, qv, bkp, b, h, q0, kt + 1, st ^ 1, tid);
            asm volatile("cp.async.wait_group 1;");
        } else {
            asm volatile("cp.async.wait_group 0;");
        }
        __syncthreads();

        uint32_t stb = sb + ASTG_BASE + st * ASTG_SZ;
        const unsigned char* bkt = (const unsigned char*)(sm + ASTG_BASE + st * ASTG_SZ + ABK_OFF);

        float S[8][4];
        #pragma unroll
        for (int nt = 0; nt < 8; nt++)
            #pragma unroll
            for (int i = 0; i < 4; i++) S[nt][i] = 0.f;

        #pragma unroll
        for (int kc = 0; kc < 4; kc++) {
            #pragma unroll
            for (int nt2 = 0; nt2 < 4; nt2++) {
                uint32_t kd = stb + AK_OFF + (uint32_t)((nt2 * 16 + ar) * 72 + kc * 16 + a8 * 8) * 2;
                uint32_t th[4];
                ldsm4(th, kd);
                uint32_t b0[2] = {th[0], th[2]}, b1[2] = {th[1], th[3]};
                mma16816h(S[2*nt2],   qhf[kc], b0);
                mma16816h(S[2*nt2+1], qhf[kc], b1);
            }
        }

        bool needMask = (kt >= 2 * qt);
        float mx0 = -1e30f, mx1 = -1e30f;
        #pragma unroll
        for (int nt = 0; nt < 8; nt++) {
            int colb = nt * 8 + tig2;
            uint32_t pb0 = *(const unsigned short*)(bkt + r0l * 64 + colb);
            uint32_t pb1 = *(const unsigned short*)(bkt + r1l * 64 + colb);
            float s0a = S[nt][0] + tb[pb0 & 0xFF];
            float s0b = S[nt][1] + tb[pb0 >> 8];
            float s1a = S[nt][2] + tb[pb1 & 0xFF];
            float s1b = S[nt][3] + tb[pb1 >> 8];
            if (needMask) {
                int kg = kt * 64 + colb;
                if (kg     > qg0) s0a = -1e30f;
                if (kg + 1 > qg0) s0b = -1e30f;
                if (kg     > qg1) s1a = -1e30f;
                if (kg + 1 > qg1) s1b = -1e30f;
            }
            S[nt][0] = s0a; S[nt][1] = s0b; S[nt][2] = s1a; S[nt][3] = s1b;
            mx0 = fmaxf(mx0, fmaxf(s0a, s0b));
            mx1 = fmaxf(mx1, fmaxf(s1a, s1b));
        }
        mx0 = fmaxf(mx0, __shfl_xor_sync(~0u, mx0, 1));
        mx0 = fmaxf(mx0, __shfl_xor_sync(~0u, mx0, 2));
        mx1 = fmaxf(mx1, __shfl_xor_sync(~0u, mx1, 1));
        mx1 = fmaxf(mx1, __shfl_xor_sync(~0u, mx1, 2));
        float mn0 = fmaxf(m0, mx0), mn1 = fmaxf(m1, mx1);
        float rs0 = __expf(m0 - mn0), rs1 = __expf(m1 - mn1);
        m0 = mn0; m1 = mn1;

        float sum0 = 0.f, sum1 = 0.f;
        #pragma unroll
        for (int nt = 0; nt < 8; nt++) {
            float p0 = __expf(S[nt][0] - mn0);
            float p1 = __expf(S[nt][1] - mn0);
            float p2 = __expf(S[nt][2] - mn1);
            float p3 = __expf(S[nt][3] - mn1);
            S[nt][0] = p0; S[nt][1] = p1; S[nt][2] = p2; S[nt][3] = p3;
            sum0 += p0 + p1; sum1 += p2 + p3;
        }
        sum0 += __shfl_xor_sync(~0u, sum0, 1); sum0 += __shfl_xor_sync(~0u, sum0, 2);
        sum1 += __shfl_xor_sync(~0u, sum1, 1); sum1 += __shfl_xor_sync(~0u, sum1, 2);
        l0 = l0 * rs0 + sum0;
        l1 = l1 * rs1 + sum1;
        #pragma unroll
        for (int nt = 0; nt < 8; nt++) {
            acc_o[nt][0] *= rs0; acc_o[nt][1] *= rs0;
            acc_o[nt][2] *= rs1; acc_o[nt][3] *= rs1;
        }

        #pragma unroll
        for (int t = 0; t < 4; t++) {
            uint32_t ap[4];
            ap[0] = pack_f16(S[2*t][0],   S[2*t][1]);
            ap[1] = pack_f16(S[2*t][2],   S[2*t][3]);
            ap[2] = pack_f16(S[2*t+1][0], S[2*t+1][1]);
            ap[3] = pack_f16(S[2*t+1][2], S[2*t+1][3]);
            #pragma unroll
            for (int j2 = 0; j2 < 4; j2++) {
                uint32_t vd = stb + AV_OFF + (uint32_t)((t * 16 + ar) * 72 + j2 * 16 + a8 * 8) * 2;
                uint32_t th[4];
                ldsm4t(th, vd);
                uint32_t b0[2] = {th[0], th[1]}, b1[2] = {th[2], th[3]};
                mma16816h(acc_o[2*j2],   ap, b0);
                mma16816h(acc_o[2*j2+1], ap, b1);
            }
        }
        __syncthreads();
    }

    float inv0 = 1.0f / l0, inv1 = 1.0f / l1;
    size_t row0 = ((size_t)(b * L_ + qg0)) * D_ + h * DH_;
    size_t row1 = ((size_t)(b * L_ + qg1)) * D_ + h * DH_;
    #pragma unroll
    for (int nt = 0; nt < 8; nt++) {
        int cc = nt * 8 + tig2;
        store_f16x2(oh, row0 + cc, acc_o[nt][0] * inv0, acc_o[nt][1] * inv0);
        store_f16x2(oh, row1 + cc, acc_o[nt][2] * inv1, acc_o[nt][3] * inv1);
    }
}

// ====================== pure LayerNorm (input already has residual) ======================
__global__ __launch_bounds__(128)
void ln_kernel(const float* __restrict__ xin,
               const float* __restrict__ g, const float* __restrict__ bb,
               float* __restrict__ xout, __half* __restrict__ oh, int writeH)
{
    __shared__ float sy[D_];
    __shared__ float red[4];
    int row = blockIdx.x;
    int tid = threadIdx.x;
    int lane = tid & 31, w = tid >> 5;

    const float* xr = xin + (size_t)row * D_;

    float lsum = 0.f;
    #pragma unroll
    for (int i = 0; i < 4; i++) {
        int d = tid + i * 128;
        float val = xr[d];
        sy[d] = val;
        lsum += val;
    }
    #pragma unroll
    for (int o = 16; o > 0; o >>= 1) lsum += __shfl_xor_sync(~0u, lsum, o);
    if (lane == 0) red[w] = lsum;
    __syncthreads();
    float mean = (red[0] + red[1] + red[2] + red[3]) * (1.0f / D_);
    __syncthreads();

    float lv = 0.f;
    #pragma unroll
    for (int i = 0; i < 4; i++) {
        int d = tid + i * 128;
        float c = sy[d] - mean;
        lv += c * c;
    }
    #pragma unroll
    for (int o = 16; o > 0; o >>= 1) lv += __shfl_xor_sync(~0u, lv, o);
    if (lane == 0) red[w] = lv;
    __syncthreads();
    float var = (red[0] + red[1] + red[2] + red[3]) * (1.0f / D_);
    float inv = rsqrtf(var + 1e-5f);

    #pragma unroll
    for (int i = 0; i < 4; i++) {
        int d = tid + i * 128;
        float val = (sy[d] - mean) * inv * g[d] + bb[d];
        xout[(size_t)row * D_ + d] = val;
        if (writeH)
            oh[(size_t)row * D_ + d] = __float2half_rn(val);
    }
}

// ====================== launch ======================
extern "C" void kernel_launch(void* const* d_in, const int* in_sizes, int n_in,
                              void* d_out, int out_size)
{
    const int*   seq      = (const int*)  d_in[0];
    const float* ts       = (const float*)d_in[1];
    const float* item_emb = (const float*)d_in[2];
    const float* pos_emb  = (const float*)d_in[3];
    const float* Wq  = (const float*)d_in[4];  const float* bq  = (const float*)d_in[5];
    const float* Wk  = (const float*)d_in[6];  const float* bk  = (const float*)d_in[7];
    const float* Wv  = (const float*)d_in[8];  const float* bv  = (const float*)d_in[9];
    const float* tbias = (const float*)d_in[10];
    const float* Wo  = (const float*)d_in[11]; const float* bo  = (const float*)d_in[12];
    const float* g1  = (const float*)d_in[13]; const float* be1 = (const float*)d_in[14];
    const float* W1  = (const float*)d_in[15]; const float* bf1 = (const float*)d_in[16];
    const float* W2  = (const float*)d_in[17]; const float* bf2 = (const float*)d_in[18];
    const float* g2  = (const float*)d_in[19]; const float* be2 = (const float*)d_in[20];

    float *x, *po, *bqkv;
    __half *ah, *fh, *qv, *wth;
    unsigned char* bkptr;
    cudaGetSymbolAddress((void**)&x,  g_x);
    cudaGetSymbolAddress((void**)&po, g_po);
    cudaGetSymbolAddress((void**)&ah, g_ah);
    cudaGetSymbolAddress((void**)&qv, g_qv);
    cudaGetSymbolAddress((void**)&fh, g_fh);
    cudaGetSymbolAddress((void**)&wth, g_wth);
    cudaGetSymbolAddress((void**)&bkptr, g_bk);
    cudaGetSymbolAddress((void**)&bqkv, g_bqkv);

    cudaFuncSetAttribute(attn_mma,  cudaFuncAttributeMaxDynamicSharedMemorySize, ATTN2_SMEM);
    cudaFuncSetAttribute(gemm_hmma, cudaFuncAttributeMaxDynamicSharedMemorySize, GSMEM);

    const size_t OQ = 0, OO = 786432, O1 = 1048576, O2 = 2097152;
    dim3 t32(32, 8);
    dim3 gQKV(NQKV / 128, ML_ / 128);  // (12, 128)
    dim3 gD(D_ / 128, ML_ / 128);      // (4, 128)
    dim3 gF(DFF_ / 128, ML_ / 128);    // (16, 128)
    dim3 ga(L_ / 128, H_, B_);         // (4, 8, 32)

    conv_wt_kernel<<<dim3(16, 16, NL_), t32>>>(Wq, wth+0,      512, 512,  (size_t)D_*D_,   WT_LAYER);
    conv_wt_kernel<<<dim3(16, 16, NL_), t32>>>(Wk, wth+262144, 512, 512,  (size_t)D_*D_,   WT_LAYER);
    conv_wt_kernel<<<dim3(16, 16, NL_), t32>>>(Wv, wth+524288, 512, 512,  (size_t)D_*D_,   WT_LAYER);
    conv_wt_kernel<<<dim3(16, 16, NL_), t32>>>(Wo, wth+OO,     512, 512,  (size_t)D_*D_,   WT_LAYER);
    conv_wt_kernel<<<dim3(64, 16, NL_), t32>>>(W1, wth+O1,     512, 2048, (size_t)D_*DFF_, WT_LAYER);
    conv_wt_kernel<<<dim3(16, 64, NL_), t32>>>(W2, wth+O2,     2048, 512, (size_t)DFF_*D_, WT_LAYER);

    biascat_kernel<<<(NL_*NQKV)/256, 256>>>(bq, bk, bv);
    embed_kernel<<<(ML_ * D_ / 4) / 256, 256>>>(seq, item_emb, pos_emb);
    bucket_kernel<<<(B_*L_*L_)/256, 256>>>(ts);

    for (int i = 0; i < NL_; i++) {
        size_t wb = (size_t)i * WT_LAYER;

        // fused QKV -> fp16 packed output, q-section scaled 0.125
        gemm_hmma<<<gQKV, 256, GSMEM>>>(ah, wth+wb+OQ, bqkv + i*NQKV,
                                        0, qv, 0, ML_, NQKV, D_, 4|8, 1.0f);

        attn_mma<<<ga, 256, ATTN2_SMEM>>>(qv, bkptr, tbias + (size_t)i*NB_*H_, ah);

        // Wo GEMM with fused residual add (po = WoOut + bias + x)
        gemm_hmma<<<gD, 256, GSMEM>>>(ah, wth+wb+OO, bo + i*D_, po, 0, x, ML_, D_, D_, 2|32, 1.0f);
        ln_kernel<<<ML_, 128>>>(po, g1 + i*D_, be1 + i*D_, x, ah, 1);

        gemm_hmma<<<gF, 256, GSMEM>>>(ah, wth+wb+O1, bf1 + i*DFF_, 0, fh, 0, ML_, DFF_, D_, 1|4, 1.0f);
        // FF2 GEMM with fused residual add (po = FF2Out + bias + x)
        gemm_hmma<<<gD, 256, GSMEM>>>(fh, wth+wb+O2, bf2 + i*D_, po, 0, x, ML_, D_, DFF_, 2|32, 1.0f);

        float* xo = (i == NL_ - 1) ? (float*)d_out : x;
        ln_kernel<<<ML_, 128>>>(po, g2 + i*D_, be2 + i*D_, xo, ah, (i < NL_ - 1) ? 1 : 0);
    }
}

// round 14
// speedup vs baseline: 1.1649x; 1.0035x over previous
#include <cuda_runtime.h>
#include <cuda_fp16.h>
#include <math.h>
#include <stdint.h>

#define B_   32
#define L_   512
#define D_   512
#define H_   8
#define DH_  64
#define NL_  2
#define DFF_ 2048
#define NB_  32
#define ML_  (B_*L_)   // 16384 rows
#define NQKV 1536

// ---------------- scratch (device globals; no allocations) ----------------
__device__ float g_x [ML_*D_];
__device__ float g_po[ML_*D_];
__device__ __align__(16) __half g_ah[ML_*D_];
__device__ __align__(16) __half g_fh[ML_*DFF_];
__device__ __align__(16) __half g_qv[ML_*NQKV];
#define WT_LAYER (4*512*512 + 2048*512 + 512*2048)
__device__ __align__(16) __half g_wth[NL_*WT_LAYER];
__device__ __align__(16) unsigned char g_bk[B_*L_*L_];
__device__ float g_bqkv[NL_*NQKV];

// ====================== PTX helpers ======================
__device__ __forceinline__ uint32_t smem_u32(const void* p) {
    uint32_t a;
    asm("{ .reg .u64 t; cvta.to.shared.u64 t, %1; cvt.u32.u64 %0, t; }" : "=r"(a) : "l"(p));
    return a;
}
__device__ __forceinline__ void cp16(uint32_t s, const void* g) {
    asm volatile("cp.async.cg.shared.global [%0], [%1], 16;" :: "r"(s), "l"(g));
}
__device__ __forceinline__ void ldsm4(uint32_t* r, uint32_t a) {
    asm volatile("ldmatrix.sync.aligned.m8n8.x4.shared.b16 {%0,%1,%2,%3}, [%4];"
        : "=r"(r[0]), "=r"(r[1]), "=r"(r[2]), "=r"(r[3]) : "r"(a));
}
__device__ __forceinline__ void ldsm4t(uint32_t* r, uint32_t a) {
    asm volatile("ldmatrix.sync.aligned.m8n8.x4.trans.shared.b16 {%0,%1,%2,%3}, [%4];"
        : "=r"(r[0]), "=r"(r[1]), "=r"(r[2]), "=r"(r[3]) : "r"(a));
}
__device__ __forceinline__ void mma16816h(float* c, const uint32_t* a, const uint32_t* b) {
    asm volatile("mma.sync.aligned.m16n8k16.row.col.f32.f16.f16.f32 "
        "{%0,%1,%2,%3}, {%4,%5,%6,%7}, {%8,%9}, {%0,%1,%2,%3};"
        : "+f"(c[0]), "+f"(c[1]), "+f"(c[2]), "+f"(c[3])
        : "r"(a[0]), "r"(a[1]), "r"(a[2]), "r"(a[3]), "r"(b[0]), "r"(b[1]));
}
__device__ __forceinline__ uint32_t pack_f16(float x, float y) {
    __half2 t = __halves2half2(__float2half_rn(x), __float2half_rn(y));
    return *(uint32_t*)&t;
}
__device__ __forceinline__ void store_f16x2(__half* O, size_t off, float v0, float v1) {
    *(uint32_t*)(O + off) = pack_f16(v0, v1);
}

// ====================== time bucket ======================
__device__ __forceinline__ int time_bucket(float delta)
{
    float a = fmaxf(fabsf(delta), 1.0f);
    const float scale = 0.71018780958489f;   // float32(log2(2592000)/30)
    int idx = (int)(log2f(a) / scale) + 1;
    idx = max(1, min(idx, NB_ - 2));
    if (a <= 1.0f)       idx = 0;
    if (a >= 2592000.0f) idx = NB_ - 1;
    return idx;
}

__global__ void bucket_kernel(const float* __restrict__ ts)
{
    int idx = blockIdx.x * blockDim.x + threadIdx.x;   // over B*L*L
    int k = idx & (L_-1);
    int q = (idx >> 9) & (L_-1);
    int b = idx >> 18;
    float d = ts[b * L_ + q] - ts[b * L_ + k];
    g_bk[idx] = (unsigned char)time_bucket(d);
}

__global__ void biascat_kernel(const float* __restrict__ bq,
                               const float* __restrict__ bk,
                               const float* __restrict__ bv)
{
    int i = blockIdx.x * blockDim.x + threadIdx.x;   // NL*1536
    int l = i / NQKV, c = i % NQKV;
    float v = (c < 512) ? bq[l*512 + c] : (c < 1024 ? bk[l*512 + c - 512] : bv[l*512 + c - 1024]);
    g_bqkv[i] = v;
}

// ====================== embedding (+ fp16) ======================
__global__ void embed_kernel(const int* __restrict__ seq,
                             const float* __restrict__ item_emb,
                             const float* __restrict__ pos_emb)
{
    int idx = blockIdx.x * blockDim.x + threadIdx.x;   // over ML*D/4
    int d4 = idx & (D_/4 - 1);
    int bl = idx >> 7;
    int l  = bl & (L_-1);
    int it = seq[bl];
    float4 a = *(const float4*)(item_emb + (size_t)it * D_ + d4*4);
    float4 p = *(const float4*)(pos_emb  + (size_t)l  * D_ + d4*4);
    a.x += p.x; a.y += p.y; a.z += p.z; a.w += p.w;
    ((float4*)g_x)[idx] = a;
    size_t off = (size_t)idx * 4;
    store_f16x2(g_ah, off,     a.x, a.y);
    store_f16x2(g_ah, off + 2, a.z, a.w);
}

// ====================== weight transpose (fp16, layer-batched) ======================
__global__ void conv_wt_kernel(const float* __restrict__ W,
                               __half* __restrict__ Th, int K, int N,
                               size_t in_stride, size_t out_stride)
{
    W  += (size_t)blockIdx.z * in_stride;
    Th += (size_t)blockIdx.z * out_stride;
    __shared__ float s[32][33];
    int tx = threadIdx.x, ty = threadIdx.y;   // 32 x 8
    int n0 = blockIdx.x * 32, k0 = blockIdx.y * 32;
    #pragma unroll
    for (int j = 0; j < 32; j += 8)
        s[ty + j][tx] = W[(size_t)(k0 + ty + j) * N + n0 + tx];
    __syncthreads();
    #pragma unroll
    for (int j = 0; j < 32; j += 8) {
        int n = n0 + ty + j, k = k0 + tx;
        Th[(size_t)n * K + k] = __float2half_rn(s[tx][ty + j]);
    }
}

// ====================== fp16 HMMA GEMM (K-chunk 32, 3-stage) ======================
#define TILE_B   10240
#define STAGE_B  20480   // 2 tiles (A, B)
#define GSMEM    61440   // 3 stages
#define STRIDE   40

// flags: 1 = relu, 2 = write fp32 C, 4 = write fp16 (Oh), 8 = qkv col-scale, 32 = add X residual
__global__ __launch_bounds__(256, 2)
void gemm_hmma(const __half* __restrict__ Ah, const __half* __restrict__ Bh,
               const float* __restrict__ bias, float* __restrict__ C,
               __half* __restrict__ Oh, const float* __restrict__ X,
               int M, int N, int K, int flags, float oscale)
{
    extern __shared__ char sm[];
    uint32_t sb = smem_u32(sm);
    int tid = threadIdx.x, lane = tid & 31, wid = tid >> 5;
    int wm = wid & 1, wn = wid >> 1;
    int m0 = blockIdx.y * 128, n0 = blockIdx.x * 128;

    int lrow = tid >> 2, lseg = tid & 3;
    const char* gAh = (const char*)(Ah + (size_t)(m0 + lrow) * K + lseg * 8);
    const char* gBh = (const char*)(Bh + (size_t)(n0 + lrow) * K + lseg * 8);
    size_t rowskip = (size_t)64 * K * 2;
    uint32_t s0off = (uint32_t)(lrow * STRIDE + lseg * 8) * 2;
    uint32_t s1off = s0off + 64 * STRIDE * 2;

    float acc[4][4][4];
    #pragma unroll
    for (int a = 0; a < 4; a++)
        #pragma unroll
        for (int b = 0; b < 4; b++)
            #pragma unroll
            for (int c = 0; c < 4; c++) acc[a][b][c] = 0.f;

    int NC = K >> 5;

#define LOADC(cc, st) do { \
    size_t ko = (size_t)(cc) * 64; \
    uint32_t s0 = sb + (st) * STAGE_B + s0off; \
    uint32_t s1 = sb + (st) * STAGE_B + s1off; \
    cp16(s0,          gAh + ko); cp16(s1,          gAh + ko + rowskip); \
    cp16(s0 + TILE_B, gBh + ko); cp16(s1 + TILE_B, gBh + ko + rowskip); \
    asm volatile("cp.async.commit_group;"); \
} while (0)

    LOADC(0, 0);
    LOADC(1, 1);

    int ar = lane & 15, a8 = lane >> 4;
    int st = 0;

    for (int c = 0; c < NC; c++) {
        if (c + 2 < NC) {
            LOADC(c + 2, (c + 2) % 3);
            asm volatile("cp.async.wait_group 2;");
        } else if (c + 1 < NC) {
            asm volatile("cp.async.wait_group 1;");
        } else {
            asm volatile("cp.async.wait_group 0;");
        }
        __syncthreads();

        uint32_t tb = sb + st * STAGE_B;
        st = (st + 1 == 3) ? 0 : st + 1;
        #pragma unroll
        for (int ks = 0; ks < 2; ks++) {
            int acol = ks * 16 + a8 * 8;
            uint32_t Ahf[4][4], Bhf[4][2];
            #pragma unroll
            for (int mt = 0; mt < 4; mt++) {
                uint32_t ad = tb + (uint32_t)((wm * 64 + mt * 16 + ar) * STRIDE + acol) * 2;
                ldsm4(Ahf[mt], ad);
            }
            #pragma unroll
            for (int p = 0; p < 2; p++) {
                uint32_t bd = tb + TILE_B +
                              (uint32_t)((wn * 32 + p * 16 + ar) * STRIDE + acol) * 2;
                uint32_t t[4];
                ldsm4(t, bd);
                Bhf[2*p][0] = t[0]; Bhf[2*p][1] = t[2];
                Bhf[2*p+1][0] = t[1]; Bhf[2*p+1][1] = t[3];
            }
            #pragma unroll
            for (int mt = 0; mt < 4; mt++)
                #pragma unroll
                for (int nt = 0; nt < 4; nt++)
                    mma16816h(acc[mt][nt], Ahf[mt], Bhf[nt]);
        }
        __syncthreads();
    }
#undef LOADC

    int relu = flags & 1, wf = flags & 2, wh = flags & 4, addx = flags & 32;
    int r_base = m0 + wm * 64 + (lane >> 2);
    int c_base = n0 + wn * 32 + (lane & 3) * 2;
    #pragma unroll
    for (int nt = 0; nt < 4; nt++) {
        int c0 = c_base + nt * 8;
        float sc = (flags & 8) ? ((c0 < 512) ? 0.125f : 1.0f) : oscale;
        float2 bv = *(const float2*)(bias + c0);
        #pragma unroll
        for (int mt = 0; mt < 4; mt++) {
            #pragma unroll
            for (int h = 0; h < 2; h++) {
                int r = r_base + mt * 16 + h * 8;
                size_t off = (size_t)r * N + c0;
                float v0 = (acc[mt][nt][h*2+0] + bv.x) * sc;
                float v1 = (acc[mt][nt][h*2+1] + bv.y) * sc;
                if (relu) { v0 = fmaxf(v0, 0.f); v1 = fmaxf(v1, 0.f); }
                if (addx) {
                    float2 xv = *(const float2*)(X + off);
                    v0 += xv.x; v1 += xv.y;
                }
                if (wf) *(float2*)(C + off) = make_float2(v0, v1);
                if (wh) store_f16x2(Oh, off, v0, v1);
            }
        }
    }
}

// ====================== fp16 HMMA flash attention (single-term, heavy-first) ======================
#define AQ_OFF    0
#define ASTG_BASE 18432
#define AK_OFF    0
#define AV_OFF    9216
#define ABK_OFF   18432
#define ASTG_SZ   26624
#define ATB_OFF   (ASTG_BASE + 2*ASTG_SZ)        // 71680
#define ATTN2_SMEM (ATB_OFF + 128)               // 71808

__device__ __forceinline__ void load_kv_tile(
    uint32_t sb, const __half* qv, const unsigned char* bkp,
    int b, int h, int q0, int kt, int st, int tid)
{
    uint32_t stb = sb + ASTG_BASE + st * ASTG_SZ;
    const char* gk = (const char*)qv + ((size_t)(b * L_) * NQKV + 512  + h * DH_) * 2;
    const char* gv = (const char*)qv + ((size_t)(b * L_) * NQKV + 1024 + h * DH_) * 2;
    #pragma unroll
    for (int i = 0; i < 2; i++) {
        int idx = tid + i * 256;
        int r = idx >> 3, c = idx & 7;
        size_t go = (size_t)(kt * 64 + r) * (NQKV * 2) + c * 16;
        uint32_t so = (uint32_t)(r * 144 + c * 16);
        cp16(stb + AK_OFF + so, gk + go);
        cp16(stb + AV_OFF + so, gv + go);
    }
    #pragma unroll
    for (int i = 0; i < 2; i++) {
        int idx = tid + i * 256;
        int r = idx >> 2, c = idx & 3;
        size_t go = ((size_t)(b * L_ + q0 + r)) * L_ + kt * 64 + c * 16;
        cp16(stb + ABK_OFF + (uint32_t)(r * 64 + c * 16), bkp + go);
    }
    asm volatile("cp.async.commit_group;");
}

__global__ __launch_bounds__(256, 2)
void attn_mma(const __half* __restrict__ qv,
              const unsigned char* __restrict__ bkp, const float* __restrict__ tbias,
              __half* __restrict__ oh)
{
    extern __shared__ char sm[];
    uint32_t sb = smem_u32(sm);
    float* smf = (float*)sm;

    // heavy-first: largest qt launches first for better tail packing
    int qt = (int)gridDim.x - 1 - (int)blockIdx.x;
    int h = blockIdx.y, b = blockIdx.z;
    int q0 = qt * 128;
    int tid = threadIdx.x, lane = tid & 31, wid = tid >> 5;
    int g = lane >> 2, tig = lane & 3, tig2 = tig * 2;
    int ar = lane & 15, a8 = lane >> 4;

    {
        const char* gq = (const char*)qv + ((size_t)(b * L_ + q0) * NQKV + h * DH_) * 2;
        #pragma unroll
        for (int i = 0; i < 4; i++) {
            int idx = tid + i * 256;
            int r = idx >> 3, c = idx & 7;
            cp16(sb + AQ_OFF + (uint32_t)(r * 144 + c * 16),
                 gq + (size_t)r * (NQKV * 2) + c * 16);
        }
    }
    if (tid < NB_) smf[ATB_OFF/4 + tid] = tbias[tid * H_ + h];

    int nkt = 2 * qt + 2;
    load_kv_tile(sb, qv, bkp, b, h, q0, 0, 0, tid);

    int qg0 = q0 + wid * 16 + g, qg1 = qg0 + 8;
    int r0l = wid * 16 + g, r1l = r0l + 8;
    float m0 = -1e30f, m1 = -1e30f, l0 = 0.f, l1 = 0.f;
    float acc_o[8][4];
    #pragma unroll
    for (int nt = 0; nt < 8; nt++)
        #pragma unroll
        for (int i = 0; i < 4; i++) acc_o[nt][i] = 0.f;

    uint32_t qhf[4][4];
    asm volatile("cp.async.wait_group 0;");
    __syncthreads();
    #pragma unroll
    for (int kc = 0; kc < 4; kc++) {
        uint32_t ad = sb + AQ_OFF + (uint32_t)((wid * 16 + ar) * 72 + kc * 16 + a8 * 8) * 2;
        ldsm4(qhf[kc], ad);
    }

    const float* tb = (const float*)(sm + ATB_OFF);

    for (int kt = 0; kt < nkt; kt++) {
        int st = kt & 1;
        if (kt + 1 < nkt) {
            load_kv_tile(sb, qv, bkp, b, h, q0, kt + 1, st ^ 1, tid);
            asm volatile("cp.async.wait_group 1;");
        } else {
            asm volatile("cp.async.wait_group 0;");
        }
        __syncthreads();

        uint32_t stb = sb + ASTG_BASE + st * ASTG_SZ;
        const unsigned char* bkt = (const unsigned char*)(sm + ASTG_BASE + st * ASTG_SZ + ABK_OFF);

        float S[8][4];
        #pragma unroll
        for (int nt = 0; nt < 8; nt++)
            #pragma unroll
            for (int i = 0; i < 4; i++) S[nt][i] = 0.f;

        #pragma unroll
        for (int kc = 0; kc < 4; kc++) {
            #pragma unroll
            for (int nt2 = 0; nt2 < 4; nt2++) {
                uint32_t kd = stb + AK_OFF + (uint32_t)((nt2 * 16 + ar) * 72 + kc * 16 + a8 * 8) * 2;
                uint32_t th[4];
                ldsm4(th, kd);
                uint32_t b0[2] = {th[0], th[2]}, b1[2] = {th[1], th[3]};
                mma16816h(S[2*nt2],   qhf[kc], b0);
                mma16816h(S[2*nt2+1], qhf[kc], b1);
            }
        }

        bool needMask = (kt >= 2 * qt);
        float mx0 = -1e30f, mx1 = -1e30f;
        #pragma unroll
        for (int nt = 0; nt < 8; nt++) {
            int colb = nt * 8 + tig2;
            uint32_t pb0 = *(const unsigned short*)(bkt + r0l * 64 + colb);
            uint32_t pb1 = *(const unsigned short*)(bkt + r1l * 64 + colb);
            float s0a = S[nt][0] + tb[pb0 & 0xFF];
            float s0b = S[nt][1] + tb[pb0 >> 8];
            float s1a = S[nt][2] + tb[pb1 & 0xFF];
            float s1b = S[nt][3] + tb[pb1 >> 8];
            if (needMask) {
                int kg = kt * 64 + colb;
                if (kg     > qg0) s0a = -1e30f;
                if (kg + 1 > qg0) s0b = -1e30f;
                if (kg     > qg1) s1a = -1e30f;
                if (kg + 1 > qg1) s1b = -1e30f;
            }
            S[nt][0] = s0a; S[nt][1] = s0b; S[nt][2] = s1a; S[nt][3] = s1b;
            mx0 = fmaxf(mx0, fmaxf(s0a, s0b));
            mx1 = fmaxf(mx1, fmaxf(s1a, s1b));
        }
        mx0 = fmaxf(mx0, __shfl_xor_sync(~0u, mx0, 1));
        mx0 = fmaxf(mx0, __shfl_xor_sync(~0u, mx0, 2));
        mx1 = fmaxf(mx1, __shfl_xor_sync(~0u, mx1, 1));
        mx1 = fmaxf(mx1, __shfl_xor_sync(~0u, mx1, 2));
        float mn0 = fmaxf(m0, mx0), mn1 = fmaxf(m1, mx1);
        float rs0 = __expf(m0 - mn0), rs1 = __expf(m1 - mn1);
        m0 = mn0; m1 = mn1;

        float sum0 = 0.f, sum1 = 0.f;
        #pragma unroll
        for (int nt = 0; nt < 8; nt++) {
            float p0 = __expf(S[nt][0] - mn0);
            float p1 = __expf(S[nt][1] - mn0);
            float p2 = __expf(S[nt][2] - mn1);
            float p3 = __expf(S[nt][3] - mn1);
            S[nt][0] = p0; S[nt][1] = p1; S[nt][2] = p2; S[nt][3] = p3;
            sum0 += p0 + p1; sum1 += p2 + p3;
        }
        sum0 += __shfl_xor_sync(~0u, sum0, 1); sum0 += __shfl_xor_sync(~0u, sum0, 2);
        sum1 += __shfl_xor_sync(~0u, sum1, 1); sum1 += __shfl_xor_sync(~0u, sum1, 2);
        l0 = l0 * rs0 + sum0;
        l1 = l1 * rs1 + sum1;
        #pragma unroll
        for (int nt = 0; nt < 8; nt++) {
            acc_o[nt][0] *= rs0; acc_o[nt][1] *= rs0;
            acc_o[nt][2] *= rs1; acc_o[nt][3] *= rs1;
        }

        #pragma unroll
        for (int t = 0; t < 4; t++) {
            uint32_t ap[4];
            ap[0] = pack_f16(S[2*t][0],   S[2*t][1]);
            ap[1] = pack_f16(S[2*t][2],   S[2*t][3]);
            ap[2] = pack_f16(S[2*t+1][0], S[2*t+1][1]);
            ap[3] = pack_f16(S[2*t+1][2], S[2*t+1][3]);
            #pragma unroll
            for (int j2 = 0; j2 < 4; j2++) {
                uint32_t vd = stb + AV_OFF + (uint32_t)((t * 16 + ar) * 72 + j2 * 16 + a8 * 8) * 2;
                uint32_t th[4];
                ldsm4t(th, vd);
                uint32_t b0[2] = {th[0], th[1]}, b1[2] = {th[2], th[3]};
                mma16816h(acc_o[2*j2],   ap, b0);
                mma16816h(acc_o[2*j2+1], ap, b1);
            }
        }
        __syncthreads();
    }

    float inv0 = 1.0f / l0, inv1 = 1.0f / l1;
    size_t row0 = ((size_t)(b * L_ + qg0)) * D_ + h * DH_;
    size_t row1 = ((size_t)(b * L_ + qg1)) * D_ + h * DH_;
    #pragma unroll
    for (int nt = 0; nt < 8; nt++) {
        int cc = nt * 8 + tig2;
        store_f16x2(oh, row0 + cc, acc_o[nt][0] * inv0, acc_o[nt][1] * inv0);
        store_f16x2(oh, row1 + cc, acc_o[nt][2] * inv1, acc_o[nt][3] * inv1);
    }
}

// ====================== pure LayerNorm (2 rows per 256-thread block) ======================
__global__ __launch_bounds__(256)
void ln_kernel(const float* __restrict__ xin,
               const float* __restrict__ g, const float* __restrict__ bb,
               float* __restrict__ xout, __half* __restrict__ oh, int writeH)
{
    __shared__ float sy[2][D_];
    __shared__ float red[2][4];
    int half = threadIdx.x >> 7;            // 0 or 1: which row
    int tid  = threadIdx.x & 127;
    int row  = blockIdx.x * 2 + half;
    int lane = tid & 31, w = tid >> 5;

    const float* xr = xin + (size_t)row * D_;

    float lsum = 0.f;
    #pragma unroll
    for (int i = 0; i < 4; i++) {
        int d = tid + i * 128;
        float val = xr[d];
        sy[half][d] = val;
        lsum += val;
    }
    #pragma unroll
    for (int o = 16; o > 0; o >>= 1) lsum += __shfl_xor_sync(~0u, lsum, o);
    if (lane == 0) red[half][w] = lsum;
    __syncthreads();
    float mean = (red[half][0] + red[half][1] + red[half][2] + red[half][3]) * (1.0f / D_);
    __syncthreads();

    float lv = 0.f;
    #pragma unroll
    for (int i = 0; i < 4; i++) {
        int d = tid + i * 128;
        float c = sy[half][d] - mean;
        lv += c * c;
    }
    #pragma unroll
    for (int o = 16; o > 0; o >>= 1) lv += __shfl_xor_sync(~0u, lv, o);
    if (lane == 0) red[half][w] = lv;
    __syncthreads();
    float var = (red[half][0] + red[half][1] + red[half][2] + red[half][3]) * (1.0f / D_);
    float inv = rsqrtf(var + 1e-5f);

    #pragma unroll
    for (int i = 0; i < 4; i++) {
        int d = tid + i * 128;
        float val = (sy[half][d] - mean) * inv * g[d] + bb[d];
        xout[(size_t)row * D_ + d] = val;
        if (writeH)
            oh[(size_t)row * D_ + d] = __float2half_rn(val);
    }
}

// ====================== launch ======================
extern "C" void kernel_launch(void* const* d_in, const int* in_sizes, int n_in,
                              void* d_out, int out_size)
{
    const int*   seq      = (const int*)  d_in[0];
    const float* ts       = (const float*)d_in[1];
    const float* item_emb = (const float*)d_in[2];
    const float* pos_emb  = (const float*)d_in[3];
    const float* Wq  = (const float*)d_in[4];  const float* bq  = (const float*)d_in[5];
    const float* Wk  = (const float*)d_in[6];  const float* bk  = (const float*)d_in[7];
    const float* Wv  = (const float*)d_in[8];  const float* bv  = (const float*)d_in[9];
    const float* tbias = (const float*)d_in[10];
    const float* Wo  = (const float*)d_in[11]; const float* bo  = (const float*)d_in[12];
    const float* g1  = (const float*)d_in[13]; const float* be1 = (const float*)d_in[14];
    const float* W1  = (const float*)d_in[15]; const float* bf1 = (const float*)d_in[16];
    const float* W2  = (const float*)d_in[17]; const float* bf2 = (const float*)d_in[18];
    const float* g2  = (const float*)d_in[19]; const float* be2 = (const float*)d_in[20];

    float *x, *po, *bqkv;
    __half *ah, *fh, *qv, *wth;
    unsigned char* bkptr;
    cudaGetSymbolAddress((void**)&x,  g_x);
    cudaGetSymbolAddress((void**)&po, g_po);
    cudaGetSymbolAddress((void**)&ah, g_ah);
    cudaGetSymbolAddress((void**)&qv, g_qv);
    cudaGetSymbolAddress((void**)&fh, g_fh);
    cudaGetSymbolAddress((void**)&wth, g_wth);
    cudaGetSymbolAddress((void**)&bkptr, g_bk);
    cudaGetSymbolAddress((void**)&bqkv, g_bqkv);

    cudaFuncSetAttribute(attn_mma,  cudaFuncAttributeMaxDynamicSharedMemorySize, ATTN2_SMEM);
    cudaFuncSetAttribute(gemm_hmma, cudaFuncAttributeMaxDynamicSharedMemorySize, GSMEM);

    const size_t OQ = 0, OO = 786432, O1 = 1048576, O2 = 2097152;
    dim3 t32(32, 8);
    dim3 gQKV(NQKV / 128, ML_ / 128);  // (12, 128)
    dim3 gD(D_ / 128, ML_ / 128);      // (4, 128)
    dim3 gF(DFF_ / 128, ML_ / 128);    // (16, 128)
    dim3 ga(L_ / 128, H_, B_);         // (4, 8, 32)

    conv_wt_kernel<<<dim3(16, 16, NL_), t32>>>(Wq, wth+0,      512, 512,  (size_t)D_*D_,   WT_LAYER);
    conv_wt_kernel<<<dim3(16, 16, NL_), t32>>>(Wk, wth+262144, 512, 512,  (size_t)D_*D_,   WT_LAYER);
    conv_wt_kernel<<<dim3(16, 16, NL_), t32>>>(Wv, wth+524288, 512, 512,  (size_t)D_*D_,   WT_LAYER);
    conv_wt_kernel<<<dim3(16, 16, NL_), t32>>>(Wo, wth+OO,     512, 512,  (size_t)D_*D_,   WT_LAYER);
    conv_wt_kernel<<<dim3(64, 16, NL_), t32>>>(W1, wth+O1,     512, 2048, (size_t)D_*DFF_, WT_LAYER);
    conv_wt_kernel<<<dim3(16, 64, NL_), t32>>>(W2, wth+O2,     2048, 512, (size_t)DFF_*D_, WT_LAYER);

    biascat_kernel<<<(NL_*NQKV)/256, 256>>>(bq, bk, bv);
    embed_kernel<<<(ML_ * D_ / 4) / 256, 256>>>(seq, item_emb, pos_emb);
    bucket_kernel<<<(B_*L_*L_)/256, 256>>>(ts);

    for (int i = 0; i < NL_; i++) {
        size_t wb = (size_t)i * WT_LAYER;

        // fused QKV -> fp16 packed output, q-section scaled 0.125
        gemm_hmma<<<gQKV, 256, GSMEM>>>(ah, wth+wb+OQ, bqkv + i*NQKV,
                                        0, qv, 0, ML_, NQKV, D_, 4|8, 1.0f);

        attn_mma<<<ga, 256, ATTN2_SMEM>>>(qv, bkptr, tbias + (size_t)i*NB_*H_, ah);

        // Wo GEMM with fused residual add (po = WoOut + bias + x)
        gemm_hmma<<<gD, 256, GSMEM>>>(ah, wth+wb+OO, bo + i*D_, po, 0, x, ML_, D_, D_, 2|32, 1.0f);
        ln_kernel<<<ML_/2, 256>>>(po, g1 + i*D_, be1 + i*D_, x, ah, 1);

        gemm_hmma<<<gF, 256, GSMEM>>>(ah, wth+wb+O1, bf1 + i*DFF_, 0, fh, 0, ML_, DFF_, D_, 1|4, 1.0f);
        // FF2 GEMM with fused residual add (po = FF2Out + bias + x)
        gemm_hmma<<<gD, 256, GSMEM>>>(fh, wth+wb+O2, bf2 + i*D_, po, 0, x, ML_, D_, DFF_, 2|32, 1.0f);

        float* xo = (i == NL_ - 1) ? (float*)d_out : x;
        ln_kernel<<<ML_/2, 256>>>(po, g2 + i*D_, be2 + i*D_, xo, ah, (i < NL_ - 1) ? 1 : 0);
    }
}

// round 15
// speedup vs baseline: 1.1791x; 1.0123x over previous
#include <cuda_runtime.h>
#include <cuda_fp16.h>
#include <math.h>
#include <stdint.h>

#define B_   32
#define L_   512
#define D_   512
#define H_   8
#define DH_  64
#define NL_  2
#define DFF_ 2048
#define NB_  32
#define ML_  (B_*L_)   // 16384 rows
#define NQKV 1536

// ---------------- scratch (device globals; no allocations) ----------------
__device__ float g_x [ML_*D_];
__device__ float g_po[ML_*D_];
__device__ __align__(16) __half g_ah[ML_*D_];
__device__ __align__(16) __half g_fh[ML_*DFF_];
__device__ __align__(16) __half g_qv[ML_*NQKV];
#define WT_LAYER (4*512*512 + 2048*512 + 512*2048)
__device__ __align__(16) __half g_wth[NL_*WT_LAYER];
__device__ __align__(16) unsigned char g_bk[B_*L_*L_];
__device__ float g_bqkv[NL_*NQKV];

// ====================== PTX helpers ======================
__device__ __forceinline__ uint32_t smem_u32(const void* p) {
    uint32_t a;
    asm("{ .reg .u64 t; cvta.to.shared.u64 t, %1; cvt.u32.u64 %0, t; }" : "=r"(a) : "l"(p));
    return a;
}
__device__ __forceinline__ void cp16(uint32_t s, const void* g) {
    asm volatile("cp.async.cg.shared.global [%0], [%1], 16;" :: "r"(s), "l"(g));
}
__device__ __forceinline__ void ldsm4(uint32_t* r, uint32_t a) {
    asm volatile("ldmatrix.sync.aligned.m8n8.x4.shared.b16 {%0,%1,%2,%3}, [%4];"
        : "=r"(r[0]), "=r"(r[1]), "=r"(r[2]), "=r"(r[3]) : "r"(a));
}
__device__ __forceinline__ void ldsm4t(uint32_t* r, uint32_t a) {
    asm volatile("ldmatrix.sync.aligned.m8n8.x4.trans.shared.b16 {%0,%1,%2,%3}, [%4];"
        : "=r"(r[0]), "=r"(r[1]), "=r"(r[2]), "=r"(r[3]) : "r"(a));
}
__device__ __forceinline__ void mma16816h(float* c, const uint32_t* a, const uint32_t* b) {
    asm volatile("mma.sync.aligned.m16n8k16.row.col.f32.f16.f16.f32 "
        "{%0,%1,%2,%3}, {%4,%5,%6,%7}, {%8,%9}, {%0,%1,%2,%3};"
        : "+f"(c[0]), "+f"(c[1]), "+f"(c[2]), "+f"(c[3])
        : "r"(a[0]), "r"(a[1]), "r"(a[2]), "r"(a[3]), "r"(b[0]), "r"(b[1]));
}
__device__ __forceinline__ uint32_t pack_f16(float x, float y) {
    __half2 t = __halves2half2(__float2half_rn(x), __float2half_rn(y));
    return *(uint32_t*)&t;
}
__device__ __forceinline__ void store_f16x2(__half* O, size_t off, float v0, float v1) {
    *(uint32_t*)(O + off) = pack_f16(v0, v1);
}

// ====================== time bucket (fast lg2.approx path) ======================
__device__ __forceinline__ int time_bucket(float delta)
{
    float a = fmaxf(fabsf(delta), 1.0f);
    const float scale = 0.71018780958489f;   // float32(log2(2592000)/30)
    int idx = (int)(__log2f(a) / scale) + 1;
    idx = max(1, min(idx, NB_ - 2));
    if (a <= 1.0f)       idx = 0;
    if (a >= 2592000.0f) idx = NB_ - 1;
    return idx;
}

__global__ void bucket_kernel(const float* __restrict__ ts)
{
    int idx = blockIdx.x * blockDim.x + threadIdx.x;   // over B*L*L
    int k = idx & (L_-1);
    int q = (idx >> 9) & (L_-1);
    int b = idx >> 18;
    float d = ts[b * L_ + q] - ts[b * L_ + k];
    g_bk[idx] = (unsigned char)time_bucket(d);
}

__global__ void biascat_kernel(const float* __restrict__ bq,
                               const float* __restrict__ bk,
                               const float* __restrict__ bv)
{
    int i = blockIdx.x * blockDim.x + threadIdx.x;   // NL*1536
    int l = i / NQKV, c = i % NQKV;
    float v = (c < 512) ? bq[l*512 + c] : (c < 1024 ? bk[l*512 + c - 512] : bv[l*512 + c - 1024]);
    g_bqkv[i] = v;
}

// ====================== embedding (+ fp16) ======================
__global__ void embed_kernel(const int* __restrict__ seq,
                             const float* __restrict__ item_emb,
                             const float* __restrict__ pos_emb)
{
    int idx = blockIdx.x * blockDim.x + threadIdx.x;   // over ML*D/4
    int d4 = idx & (D_/4 - 1);
    int bl = idx >> 7;
    int l  = bl & (L_-1);
    int it = seq[bl];
    float4 a = *(const float4*)(item_emb + (size_t)it * D_ + d4*4);
    float4 p = *(const float4*)(pos_emb  + (size_t)l  * D_ + d4*4);
    a.x += p.x; a.y += p.y; a.z += p.z; a.w += p.w;
    ((float4*)g_x)[idx] = a;
    size_t off = (size_t)idx * 4;
    store_f16x2(g_ah, off,     a.x, a.y);
    store_f16x2(g_ah, off + 2, a.z, a.w);
}

// ====================== weight transpose (fp16, layer-batched) ======================
__global__ void conv_wt_kernel(const float* __restrict__ W,
                               __half* __restrict__ Th, int K, int N,
                               size_t in_stride, size_t out_stride)
{
    W  += (size_t)blockIdx.z * in_stride;
    Th += (size_t)blockIdx.z * out_stride;
    __shared__ float s[32][33];
    int tx = threadIdx.x, ty = threadIdx.y;   // 32 x 8
    int n0 = blockIdx.x * 32, k0 = blockIdx.y * 32;
    #pragma unroll
    for (int j = 0; j < 32; j += 8)
        s[ty + j][tx] = W[(size_t)(k0 + ty + j) * N + n0 + tx];
    __syncthreads();
    #pragma unroll
    for (int j = 0; j < 32; j += 8) {
        int n = n0 + ty + j, k = k0 + tx;
        Th[(size_t)n * K + k] = __float2half_rn(s[tx][ty + j]);
    }
}

// ====================== fp16 HMMA GEMM (K-chunk 32, 3-stage, single-sync) ======================
#define TILE_B   10240
#define STAGE_B  20480   // 2 tiles (A, B)
#define GSMEM    61440   // 3 stages
#define STRIDE   40

// flags: 1 = relu, 2 = write fp32 C, 4 = write fp16 (Oh), 8 = qkv col-scale, 32 = add X residual
__global__ __launch_bounds__(256, 2)
void gemm_hmma(const __half* __restrict__ Ah, const __half* __restrict__ Bh,
               const float* __restrict__ bias, float* __restrict__ C,
               __half* __restrict__ Oh, const float* __restrict__ X,
               int M, int N, int K, int flags, float oscale)
{
    extern __shared__ char sm[];
    uint32_t sb = smem_u32(sm);
    int tid = threadIdx.x, lane = tid & 31, wid = tid >> 5;
    int wm = wid & 1, wn = wid >> 1;
    int m0 = blockIdx.y * 128, n0 = blockIdx.x * 128;

    int lrow = tid >> 2, lseg = tid & 3;
    const char* gAh = (const char*)(Ah + (size_t)(m0 + lrow) * K + lseg * 8);
    const char* gBh = (const char*)(Bh + (size_t)(n0 + lrow) * K + lseg * 8);
    size_t rowskip = (size_t)64 * K * 2;
    uint32_t s0off = (uint32_t)(lrow * STRIDE + lseg * 8) * 2;
    uint32_t s1off = s0off + 64 * STRIDE * 2;

    float acc[4][4][4];
    #pragma unroll
    for (int a = 0; a < 4; a++)
        #pragma unroll
        for (int b = 0; b < 4; b++)
            #pragma unroll
            for (int c = 0; c < 4; c++) acc[a][b][c] = 0.f;

    int NC = K >> 5;

#define LOADC(cc, st) do { \
    size_t ko = (size_t)(cc) * 64; \
    uint32_t s0 = sb + (st) * STAGE_B + s0off; \
    uint32_t s1 = sb + (st) * STAGE_B + s1off; \
    cp16(s0,          gAh + ko); cp16(s1,          gAh + ko + rowskip); \
    cp16(s0 + TILE_B, gBh + ko); cp16(s1 + TILE_B, gBh + ko + rowskip); \
    asm volatile("cp.async.commit_group;"); \
} while (0)

    LOADC(0, 0);
    LOADC(1, 1);

    int ar = lane & 15, a8 = lane >> 4;
    int st = 0;

    for (int c = 0; c < NC; c++) {
        if (c + 1 < NC) {
            asm volatile("cp.async.wait_group 1;");
        } else {
            asm volatile("cp.async.wait_group 0;");
        }
        __syncthreads();
        // safe: all warps passed the sync => finished reading stage (c+2)%3 == (c-1)%3
        if (c + 2 < NC) LOADC(c + 2, (c + 2) % 3);

        uint32_t tb = sb + st * STAGE_B;
        st = (st + 1 == 3) ? 0 : st + 1;
        #pragma unroll
        for (int ks = 0; ks < 2; ks++) {
            int acol = ks * 16 + a8 * 8;
            uint32_t Ahf[4][4], Bhf[4][2];
            #pragma unroll
            for (int mt = 0; mt < 4; mt++) {
                uint32_t ad = tb + (uint32_t)((wm * 64 + mt * 16 + ar) * STRIDE + acol) * 2;
                ldsm4(Ahf[mt], ad);
            }
            #pragma unroll
            for (int p = 0; p < 2; p++) {
                uint32_t bd = tb + TILE_B +
                              (uint32_t)((wn * 32 + p * 16 + ar) * STRIDE + acol) * 2;
                uint32_t t[4];
                ldsm4(t, bd);
                Bhf[2*p][0] = t[0]; Bhf[2*p][1] = t[2];
                Bhf[2*p+1][0] = t[1]; Bhf[2*p+1][1] = t[3];
            }
            #pragma unroll
            for (int mt = 0; mt < 4; mt++)
                #pragma unroll
                for (int nt = 0; nt < 4; nt++)
                    mma16816h(acc[mt][nt], Ahf[mt], Bhf[nt]);
        }
    }
#undef LOADC

    int relu = flags & 1, wf = flags & 2, wh = flags & 4, addx = flags & 32;
    int r_base = m0 + wm * 64 + (lane >> 2);
    int c_base = n0 + wn * 32 + (lane & 3) * 2;
    #pragma unroll
    for (int nt = 0; nt < 4; nt++) {
        int c0 = c_base + nt * 8;
        float sc = (flags & 8) ? ((c0 < 512) ? 0.125f : 1.0f) : oscale;
        float2 bv = *(const float2*)(bias + c0);
        #pragma unroll
        for (int mt = 0; mt < 4; mt++) {
            #pragma unroll
            for (int h = 0; h < 2; h++) {
                int r = r_base + mt * 16 + h * 8;
                size_t off = (size_t)r * N + c0;
                float v0 = (acc[mt][nt][h*2+0] + bv.x) * sc;
                float v1 = (acc[mt][nt][h*2+1] + bv.y) * sc;
                if (relu) { v0 = fmaxf(v0, 0.f); v1 = fmaxf(v1, 0.f); }
                if (addx) {
                    float2 xv = *(const float2*)(X + off);
                    v0 += xv.x; v1 += xv.y;
                }
                if (wf) *(float2*)(C + off) = make_float2(v0, v1);
                if (wh) store_f16x2(Oh, off, v0, v1);
            }
        }
    }
}

// ====================== fp16 HMMA flash attention (single-term, single-sync) ======================
#define AQ_OFF    0
#define ASTG_BASE 18432
#define AK_OFF    0
#define AV_OFF    9216
#define ABK_OFF   18432
#define ASTG_SZ   26624
#define ATB_OFF   (ASTG_BASE + 2*ASTG_SZ)        // 71680
#define ATTN2_SMEM (ATB_OFF + 128)               // 71808

__device__ __forceinline__ void load_kv_tile(
    uint32_t sb, const __half* qv, const unsigned char* bkp,
    int b, int h, int q0, int kt, int st, int tid)
{
    uint32_t stb = sb + ASTG_BASE + st * ASTG_SZ;
    const char* gk = (const char*)qv + ((size_t)(b * L_) * NQKV + 512  + h * DH_) * 2;
    const char* gv = (const char*)qv + ((size_t)(b * L_) * NQKV + 1024 + h * DH_) * 2;
    #pragma unroll
    for (int i = 0; i < 2; i++) {
        int idx = tid + i * 256;
        int r = idx >> 3, c = idx & 7;
        size_t go = (size_t)(kt * 64 + r) * (NQKV * 2) + c * 16;
        uint32_t so = (uint32_t)(r * 144 + c * 16);
        cp16(stb + AK_OFF + so, gk + go);
        cp16(stb + AV_OFF + so, gv + go);
    }
    #pragma unroll
    for (int i = 0; i < 2; i++) {
        int idx = tid + i * 256;
        int r = idx >> 2, c = idx & 3;
        size_t go = ((size_t)(b * L_ + q0 + r)) * L_ + kt * 64 + c * 16;
        cp16(stb + ABK_OFF + (uint32_t)(r * 64 + c * 16), bkp + go);
    }
    asm volatile("cp.async.commit_group;");
}

__global__ __launch_bounds__(256, 2)
void attn_mma(const __half* __restrict__ qv,
              const unsigned char* __restrict__ bkp, const float* __restrict__ tbias,
              __half* __restrict__ oh)
{
    extern __shared__ char sm[];
    uint32_t sb = smem_u32(sm);
    float* smf = (float*)sm;

    int qt = (int)gridDim.x - 1 - (int)blockIdx.x;   // heavy-first
    int h = blockIdx.y, b = blockIdx.z;
    int q0 = qt * 128;
    int tid = threadIdx.x, lane = tid & 31, wid = tid >> 5;
    int g = lane >> 2, tig = lane & 3, tig2 = tig * 2;
    int ar = lane & 15, a8 = lane >> 4;

    {
        const char* gq = (const char*)qv + ((size_t)(b * L_ + q0) * NQKV + h * DH_) * 2;
        #pragma unroll
        for (int i = 0; i < 4; i++) {
            int idx = tid + i * 256;
            int r = idx >> 3, c = idx & 7;
            cp16(sb + AQ_OFF + (uint32_t)(r * 144 + c * 16),
                 gq + (size_t)r * (NQKV * 2) + c * 16);
        }
    }
    if (tid < NB_) smf[ATB_OFF/4 + tid] = tbias[tid * H_ + h];

    int nkt = 2 * qt + 2;
    load_kv_tile(sb, qv, bkp, b, h, q0, 0, 0, tid);

    int qg0 = q0 + wid * 16 + g, qg1 = qg0 + 8;
    int r0l = wid * 16 + g, r1l = r0l + 8;
    float m0 = -1e30f, m1 = -1e30f, l0 = 0.f, l1 = 0.f;
    float acc_o[8][4];
    #pragma unroll
    for (int nt = 0; nt < 8; nt++)
        #pragma unroll
        for (int i = 0; i < 4; i++) acc_o[nt][i] = 0.f;

    uint32_t qhf[4][4];
    asm volatile("cp.async.wait_group 0;");
    __syncthreads();
    #pragma unroll
    for (int kc = 0; kc < 4; kc++) {
        uint32_t ad = sb + AQ_OFF + (uint32_t)((wid * 16 + ar) * 72 + kc * 16 + a8 * 8) * 2;
        ldsm4(qhf[kc], ad);
    }

    const float* tb = (const float*)(sm + ATB_OFF);

    for (int kt = 0; kt < nkt; kt++) {
        int st = kt & 1;
        asm volatile("cp.async.wait_group 0;");   // tile kt ready (sole outstanding group)
        __syncthreads();
        // safe: all warps passed the sync => done reading stage st^1 (from iter kt-1)
        if (kt + 1 < nkt) load_kv_tile(sb, qv, bkp, b, h, q0, kt + 1, st ^ 1, tid);

        uint32_t stb = sb + ASTG_BASE + st * ASTG_SZ;
        const unsigned char* bkt = (const unsigned char*)(sm + ASTG_BASE + st * ASTG_SZ + ABK_OFF);

        float S[8][4];
        #pragma unroll
        for (int nt = 0; nt < 8; nt++)
            #pragma unroll
            for (int i = 0; i < 4; i++) S[nt][i] = 0.f;

        #pragma unroll
        for (int kc = 0; kc < 4; kc++) {
            #pragma unroll
            for (int nt2 = 0; nt2 < 4; nt2++) {
                uint32_t kd = stb + AK_OFF + (uint32_t)((nt2 * 16 + ar) * 72 + kc * 16 + a8 * 8) * 2;
                uint32_t th[4];
                ldsm4(th, kd);
                uint32_t b0[2] = {th[0], th[2]}, b1[2] = {th[1], th[3]};
                mma16816h(S[2*nt2],   qhf[kc], b0);
                mma16816h(S[2*nt2+1], qhf[kc], b1);
            }
        }

        bool needMask = (kt >= 2 * qt);
        float mx0 = -1e30f, mx1 = -1e30f;
        #pragma unroll
        for (int nt = 0; nt < 8; nt++) {
            int colb = nt * 8 + tig2;
            uint32_t pb0 = *(const unsigned short*)(bkt + r0l * 64 + colb);
            uint32_t pb1 = *(const unsigned short*)(bkt + r1l * 64 + colb);
            float s0a = S[nt][0] + tb[pb0 & 0xFF];
            float s0b = S[nt][1] + tb[pb0 >> 8];
            float s1a = S[nt][2] + tb[pb1 & 0xFF];
            float s1b = S[nt][3] + tb[pb1 >> 8];
            if (needMask) {
                int kg = kt * 64 + colb;
                if (kg     > qg0) s0a = -1e30f;
                if (kg + 1 > qg0) s0b = -1e30f;
                if (kg     > qg1) s1a = -1e30f;
                if (kg + 1 > qg1) s1b = -1e30f;
            }
            S[nt][0] = s0a; S[nt][1] = s0b; S[nt][2] = s1a; S[nt][3] = s1b;
            mx0 = fmaxf(mx0, fmaxf(s0a, s0b));
            mx1 = fmaxf(mx1, fmaxf(s1a, s1b));
        }
        mx0 = fmaxf(mx0, __shfl_xor_sync(~0u, mx0, 1));
        mx0 = fmaxf(mx0, __shfl_xor_sync(~0u, mx0, 2));
        mx1 = fmaxf(mx1, __shfl_xor_sync(~0u, mx1, 1));
        mx1 = fmaxf(mx1, __shfl_xor_sync(~0u, mx1, 2));
        float mn0 = fmaxf(m0, mx0), mn1 = fmaxf(m1, mx1);
        float rs0 = __expf(m0 - mn0), rs1 = __expf(m1 - mn1);
        m0 = mn0; m1 = mn1;

        float sum0 = 0.f, sum1 = 0.f;
        #pragma unroll
        for (int nt = 0; nt < 8; nt++) {
            float p0 = __expf(S[nt][0] - mn0);
            float p1 = __expf(S[nt][1] - mn0);
            float p2 = __expf(S[nt][2] - mn1);
            float p3 = __expf(S[nt][3] - mn1);
            S[nt][0] = p0; S[nt][1] = p1; S[nt][2] = p2; S[nt][3] = p3;
            sum0 += p0 + p1; sum1 += p2 + p3;
        }
        sum0 += __shfl_xor_sync(~0u, sum0, 1); sum0 += __shfl_xor_sync(~0u, sum0, 2);
        sum1 += __shfl_xor_sync(~0u, sum1, 1); sum1 += __shfl_xor_sync(~0u, sum1, 2);
        l0 = l0 * rs0 + sum0;
        l1 = l1 * rs1 + sum1;
        #pragma unroll
        for (int nt = 0; nt < 8; nt++) {
            acc_o[nt][0] *= rs0; acc_o[nt][1] *= rs0;
            acc_o[nt][2] *= rs1; acc_o[nt][3] *= rs1;
        }

        #pragma unroll
        for (int t = 0; t < 4; t++) {
            uint32_t ap[4];
            ap[0] = pack_f16(S[2*t][0],   S[2*t][1]);
            ap[1] = pack_f16(S[2*t][2],   S[2*t][3]);
            ap[2] = pack_f16(S[2*t+1][0], S[2*t+1][1]);
            ap[3] = pack_f16(S[2*t+1][2], S[2*t+1][3]);
            #pragma unroll
            for (int j2 = 0; j2 < 4; j2++) {
                uint32_t vd = stb + AV_OFF + (uint32_t)((t * 16 + ar) * 72 + j2 * 16 + a8 * 8) * 2;
                uint32_t th[4];
                ldsm4t(th, vd);
                uint32_t b0[2] = {th[0], th[1]}, b1[2] = {th[2], th[3]};
                mma16816h(acc_o[2*j2],   ap, b0);
                mma16816h(acc_o[2*j2+1], ap, b1);
            }
        }
    }

    float inv0 = 1.0f / l0, inv1 = 1.0f / l1;
    size_t row0 = ((size_t)(b * L_ + qg0)) * D_ + h * DH_;
    size_t row1 = ((size_t)(b * L_ + qg1)) * D_ + h * DH_;
    #pragma unroll
    for (int nt = 0; nt < 8; nt++) {
        int cc = nt * 8 + tig2;
        store_f16x2(oh, row0 + cc, acc_o[nt][0] * inv0, acc_o[nt][1] * inv0);
        store_f16x2(oh, row1 + cc, acc_o[nt][2] * inv1, acc_o[nt][3] * inv1);
    }
}

// ====================== pure LayerNorm (2 rows per 256-thread block) ======================
__global__ __launch_bounds__(256)
void ln_kernel(const float* __restrict__ xin,
               const float* __restrict__ g, const float* __restrict__ bb,
               float* __restrict__ xout, __half* __restrict__ oh, int writeH)
{
    __shared__ float sy[2][D_];
    __shared__ float red[2][4];
    int half = threadIdx.x >> 7;
    int tid  = threadIdx.x & 127;
    int row  = blockIdx.x * 2 + half;
    int lane = tid & 31, w = tid >> 5;

    const float* xr = xin + (size_t)row * D_;

    float lsum = 0.f;
    #pragma unroll
    for (int i = 0; i < 4; i++) {
        int d = tid + i * 128;
        float val = xr[d];
        sy[half][d] = val;
        lsum += val;
    }
    #pragma unroll
    for (int o = 16; o > 0; o >>= 1) lsum += __shfl_xor_sync(~0u, lsum, o);
    if (lane == 0) red[half][w] = lsum;
    __syncthreads();
    float mean = (red[half][0] + red[half][1] + red[half][2] + red[half][3]) * (1.0f / D_);
    __syncthreads();

    float lv = 0.f;
    #pragma unroll
    for (int i = 0; i < 4; i++) {
        int d = tid + i * 128;
        float c = sy[half][d] - mean;
        lv += c * c;
    }
    #pragma unroll
    for (int o = 16; o > 0; o >>= 1) lv += __shfl_xor_sync(~0u, lv, o);
    if (lane == 0) red[half][w] = lv;
    __syncthreads();
    float var = (red[half][0] + red[half][1] + red[half][2] + red[half][3]) * (1.0f / D_);
    float inv = rsqrtf(var + 1e-5f);

    #pragma unroll
    for (int i = 0; i < 4; i++) {
        int d = tid + i * 128;
        float val = (sy[half][d] - mean) * inv * g[d] + bb[d];
        xout[(size_t)row * D_ + d] = val;
        if (writeH)
            oh[(size_t)row * D_ + d] = __float2half_rn(val);
    }
}

// ====================== launch ======================
extern "C" void kernel_launch(void* const* d_in, const int* in_sizes, int n_in,
                              void* d_out, int out_size)
{
    const int*   seq      = (const int*)  d_in[0];
    const float* ts       = (const float*)d_in[1];
    const float* item_emb = (const float*)d_in[2];
    const float* pos_emb  = (const float*)d_in[3];
    const float* Wq  = (const float*)d_in[4];  const float* bq  = (const float*)d_in[5];
    const float* Wk  = (const float*)d_in[6];  const float* bk  = (const float*)d_in[7];
    const float* Wv  = (const float*)d_in[8];  const float* bv  = (const float*)d_in[9];
    const float* tbias = (const float*)d_in[10];
    const float* Wo  = (const float*)d_in[11]; const float* bo  = (const float*)d_in[12];
    const float* g1  = (const float*)d_in[13]; const float* be1 = (const float*)d_in[14];
    const float* W1  = (const float*)d_in[15]; const float* bf1 = (const float*)d_in[16];
    const float* W2  = (const float*)d_in[17]; const float* bf2 = (const float*)d_in[18];
    const float* g2  = (const float*)d_in[19]; const float* be2 = (const float*)d_in[20];

    float *x, *po, *bqkv;
    __half *ah, *fh, *qv, *wth;
    unsigned char* bkptr;
    cudaGetSymbolAddress((void**)&x,  g_x);
    cudaGetSymbolAddress((void**)&po, g_po);
    cudaGetSymbolAddress((void**)&ah, g_ah);
    cudaGetSymbolAddress((void**)&qv, g_qv);
    cudaGetSymbolAddress((void**)&fh, g_fh);
    cudaGetSymbolAddress((void**)&wth, g_wth);
    cudaGetSymbolAddress((void**)&bkptr, g_bk);
    cudaGetSymbolAddress((void**)&bqkv, g_bqkv);

    cudaFuncSetAttribute(attn_mma,  cudaFuncAttributeMaxDynamicSharedMemorySize, ATTN2_SMEM);
    cudaFuncSetAttribute(gemm_hmma, cudaFuncAttributeMaxDynamicSharedMemorySize, GSMEM);

    const size_t OQ = 0, OO = 786432, O1 = 1048576, O2 = 2097152;
    dim3 t32(32, 8);
    dim3 gQKV(NQKV / 128, ML_ / 128);  // (12, 128)
    dim3 gD(D_ / 128, ML_ / 128);      // (4, 128)
    dim3 gF(DFF_ / 128, ML_ / 128);    // (16, 128)
    dim3 ga(L_ / 128, H_, B_);         // (4, 8, 32)

    conv_wt_kernel<<<dim3(16, 16, NL_), t32>>>(Wq, wth+0,      512, 512,  (size_t)D_*D_,   WT_LAYER);
    conv_wt_kernel<<<dim3(16, 16, NL_), t32>>>(Wk, wth+262144, 512, 512,  (size_t)D_*D_,   WT_LAYER);
    conv_wt_kernel<<<dim3(16, 16, NL_), t32>>>(Wv, wth+524288, 512, 512,  (size_t)D_*D_,   WT_LAYER);
    conv_wt_kernel<<<dim3(16, 16, NL_), t32>>>(Wo, wth+OO,     512, 512,  (size_t)D_*D_,   WT_LAYER);
    conv_wt_kernel<<<dim3(64, 16, NL_), t32>>>(W1, wth+O1,     512, 2048, (size_t)D_*DFF_, WT_LAYER);
    conv_wt_kernel<<<dim3(16, 64, NL_), t32>>>(W2, wth+O2,     2048, 512, (size_t)DFF_*D_, WT_LAYER);

    biascat_kernel<<<(NL_*NQKV)/256, 256>>>(bq, bk, bv);
    embed_kernel<<<(ML_ * D_ / 4) / 256, 256>>>(seq, item_emb, pos_emb);
    bucket_kernel<<<(B_*L_*L_)/256, 256>>>(ts);

    for (int i = 0; i < NL_; i++) {
        size_t wb = (size_t)i * WT_LAYER;

        // fused QKV -> fp16 packed output, q-section scaled 0.125
        gemm_hmma<<<gQKV, 256, GSMEM>>>(ah, wth+wb+OQ, bqkv + i*NQKV,
                                        0, qv, 0, ML_, NQKV, D_, 4|8, 1.0f);

        attn_mma<<<ga, 256, ATTN2_SMEM>>>(qv, bkptr, tbias + (size_t)i*NB_*H_, ah);

        // Wo GEMM with fused residual add (po = WoOut + bias + x)
        gemm_hmma<<<gD, 256, GSMEM>>>(ah, wth+wb+OO, bo + i*D_, po, 0, x, ML_, D_, D_, 2|32, 1.0f);
        ln_kernel<<<ML_/2, 256>>>(po, g1 + i*D_, be1 + i*D_, x, ah, 1);

        gemm_hmma<<<gF, 256, GSMEM>>>(ah, wth+wb+O1, bf1 + i*DFF_, 0, fh, 0, ML_, DFF_, D_, 1|4, 1.0f);
        // FF2 GEMM with fused residual add (po = FF2Out + bias + x)
        gemm_hmma<<<gD, 256, GSMEM>>>(fh, wth+wb+O2, bf2 + i*D_, po, 0, x, ML_, D_, DFF_, 2|32, 1.0f);

        float* xo = (i == NL_ - 1) ? (float*)d_out : x;
        ln_kernel<<<ML_/2, 256>>>(po, g2 + i*D_, be2 + i*D_, xo, ah, (i < NL_ - 1) ? 1 : 0);
    }
}

// round 16
// speedup vs baseline: 1.1806x; 1.0013x over previous
#include <cuda_runtime.h>
#include <cuda_fp16.h>
#include <math.h>
#include <stdint.h>

#define B_   32
#define L_   512
#define D_   512
#define H_   8
#define DH_  64
#define NL_  2
#define DFF_ 2048
#define NB_  32
#define ML_  (B_*L_)   // 16384 rows
#define NQKV 1536

// ---------------- scratch (device globals; no allocations) ----------------
__device__ float g_x [ML_*D_];
__device__ float g_po[ML_*D_];
__device__ __align__(16) __half g_ah[ML_*D_];
__device__ __align__(16) __half g_fh[ML_*DFF_];
__device__ __align__(16) __half g_qv[ML_*NQKV];
#define WT_LAYER (4*512*512 + 2048*512 + 512*2048)
__device__ __align__(16) __half g_wth[NL_*WT_LAYER];
__device__ __align__(16) unsigned char g_bk[B_*L_*L_];
__device__ float g_bqkv[NL_*NQKV];

// ====================== PTX helpers ======================
__device__ __forceinline__ uint32_t smem_u32(const void* p) {
    uint32_t a;
    asm("{ .reg .u64 t; cvta.to.shared.u64 t, %1; cvt.u32.u64 %0, t; }" : "=r"(a) : "l"(p));
    return a;
}
__device__ __forceinline__ void cp16(uint32_t s, const void* g) {
    asm volatile("cp.async.cg.shared.global [%0], [%1], 16;" :: "r"(s), "l"(g));
}
__device__ __forceinline__ void ldsm4(uint32_t* r, uint32_t a) {
    asm volatile("ldmatrix.sync.aligned.m8n8.x4.shared.b16 {%0,%1,%2,%3}, [%4];"
        : "=r"(r[0]), "=r"(r[1]), "=r"(r[2]), "=r"(r[3]) : "r"(a));
}
__device__ __forceinline__ void ldsm4t(uint32_t* r, uint32_t a) {
    asm volatile("ldmatrix.sync.aligned.m8n8.x4.trans.shared.b16 {%0,%1,%2,%3}, [%4];"
        : "=r"(r[0]), "=r"(r[1]), "=r"(r[2]), "=r"(r[3]) : "r"(a));
}
__device__ __forceinline__ void mma16816h(float* c, const uint32_t* a, const uint32_t* b) {
    asm volatile("mma.sync.aligned.m16n8k16.row.col.f32.f16.f16.f32 "
        "{%0,%1,%2,%3}, {%4,%5,%6,%7}, {%8,%9}, {%0,%1,%2,%3};"
        : "+f"(c[0]), "+f"(c[1]), "+f"(c[2]), "+f"(c[3])
        : "r"(a[0]), "r"(a[1]), "r"(a[2]), "r"(a[3]), "r"(b[0]), "r"(b[1]));
}
__device__ __forceinline__ uint32_t pack_f16(float x, float y) {
    __half2 t = __halves2half2(__float2half_rn(x), __float2half_rn(y));
    return *(uint32_t*)&t;
}
__device__ __forceinline__ void store_f16x2(__half* O, size_t off, float v0, float v1) {
    *(uint32_t*)(O + off) = pack_f16(v0, v1);
}

// ====================== time bucket (fast lg2.approx path) ======================
__device__ __forceinline__ int time_bucket(float delta)
{
    float a = fmaxf(fabsf(delta), 1.0f);
    const float scale = 0.71018780958489f;   // float32(log2(2592000)/30)
    int idx = (int)(__log2f(a) / scale) + 1;
    idx = max(1, min(idx, NB_ - 2));
    if (a <= 1.0f)       idx = 0;
    if (a >= 2592000.0f) idx = NB_ - 1;
    return idx;
}

__global__ void bucket_kernel(const float* __restrict__ ts)
{
    int idx = blockIdx.x * blockDim.x + threadIdx.x;   // over B*L*L
    int k = idx & (L_-1);
    int q = (idx >> 9) & (L_-1);
    int b = idx >> 18;
    float d = ts[b * L_ + q] - ts[b * L_ + k];
    g_bk[idx] = (unsigned char)time_bucket(d);
}

__global__ void biascat_kernel(const float* __restrict__ bq,
                               const float* __restrict__ bk,
                               const float* __restrict__ bv)
{
    int i = blockIdx.x * blockDim.x + threadIdx.x;   // NL*1536
    int l = i / NQKV, c = i % NQKV;
    float v = (c < 512) ? bq[l*512 + c] : (c < 1024 ? bk[l*512 + c - 512] : bv[l*512 + c - 1024]);
    g_bqkv[i] = v;
}

// ====================== embedding (+ fp16) ======================
__global__ void embed_kernel(const int* __restrict__ seq,
                             const float* __restrict__ item_emb,
                             const float* __restrict__ pos_emb)
{
    int idx = blockIdx.x * blockDim.x + threadIdx.x;   // over ML*D/4
    int d4 = idx & (D_/4 - 1);
    int bl = idx >> 7;
    int l  = bl & (L_-1);
    int it = seq[bl];
    float4 a = *(const float4*)(item_emb + (size_t)it * D_ + d4*4);
    float4 p = *(const float4*)(pos_emb  + (size_t)l  * D_ + d4*4);
    a.x += p.x; a.y += p.y; a.z += p.z; a.w += p.w;
    ((float4*)g_x)[idx] = a;
    size_t off = (size_t)idx * 4;
    store_f16x2(g_ah, off,     a.x, a.y);
    store_f16x2(g_ah, off + 2, a.z, a.w);
}

// ====================== weight transpose (fp16, layer-batched) ======================
__global__ void conv_wt_kernel(const float* __restrict__ W,
                               __half* __restrict__ Th, int K, int N,
                               size_t in_stride, size_t out_stride)
{
    W  += (size_t)blockIdx.z * in_stride;
    Th += (size_t)blockIdx.z * out_stride;
    __shared__ float s[32][33];
    int tx = threadIdx.x, ty = threadIdx.y;   // 32 x 8
    int n0 = blockIdx.x * 32, k0 = blockIdx.y * 32;
    #pragma unroll
    for (int j = 0; j < 32; j += 8)
        s[ty + j][tx] = W[(size_t)(k0 + ty + j) * N + n0 + tx];
    __syncthreads();
    #pragma unroll
    for (int j = 0; j < 32; j += 8) {
        int n = n0 + ty + j, k = k0 + tx;
        Th[(size_t)n * K + k] = __float2half_rn(s[tx][ty + j]);
    }
}

// ====================== fp16 HMMA GEMM (K-chunk 32, 3-stage, single-sync) ======================
#define TILE_B   10240
#define STAGE_B  20480   // 2 tiles (A, B)
#define GSMEM    61440   // 3 stages
#define STRIDE   40

// flags: 1 = relu, 2 = write fp32 C, 4 = write fp16 (Oh), 8 = qkv col-scale, 32 = add X residual
__global__ __launch_bounds__(256, 2)
void gemm_hmma(const __half* __restrict__ Ah, const __half* __restrict__ Bh,
               const float* __restrict__ bias, float* __restrict__ C,
               __half* __restrict__ Oh, const float* __restrict__ X,
               int M, int N, int K, int flags, float oscale)
{
    extern __shared__ char sm[];
    uint32_t sb = smem_u32(sm);
    int tid = threadIdx.x, lane = tid & 31, wid = tid >> 5;
    int wm = wid & 1, wn = wid >> 1;
    int m0 = blockIdx.y * 128, n0 = blockIdx.x * 128;

    int lrow = tid >> 2, lseg = tid & 3;
    const char* gAh = (const char*)(Ah + (size_t)(m0 + lrow) * K + lseg * 8);
    const char* gBh = (const char*)(Bh + (size_t)(n0 + lrow) * K + lseg * 8);
    size_t rowskip = (size_t)64 * K * 2;
    uint32_t s0off = (uint32_t)(lrow * STRIDE + lseg * 8) * 2;
    uint32_t s1off = s0off + 64 * STRIDE * 2;

    float acc[4][4][4];
    #pragma unroll
    for (int a = 0; a < 4; a++)
        #pragma unroll
        for (int b = 0; b < 4; b++)
            #pragma unroll
            for (int c = 0; c < 4; c++) acc[a][b][c] = 0.f;

    int NC = K >> 5;

#define LOADC(cc, st) do { \
    size_t ko = (size_t)(cc) * 64; \
    uint32_t s0 = sb + (st) * STAGE_B + s0off; \
    uint32_t s1 = sb + (st) * STAGE_B + s1off; \
    cp16(s0,          gAh + ko); cp16(s1,          gAh + ko + rowskip); \
    cp16(s0 + TILE_B, gBh + ko); cp16(s1 + TILE_B, gBh + ko + rowskip); \
    asm volatile("cp.async.commit_group;"); \
} while (0)

    LOADC(0, 0);
    LOADC(1, 1);

    int ar = lane & 15, a8 = lane >> 4;
    int st = 0;

    for (int c = 0; c < NC; c++) {
        if (c + 1 < NC) {
            asm volatile("cp.async.wait_group 1;");
        } else {
            asm volatile("cp.async.wait_group 0;");
        }
        __syncthreads();
        if (c + 2 < NC) LOADC(c + 2, (c + 2) % 3);

        uint32_t tb = sb + st * STAGE_B;
        st = (st + 1 == 3) ? 0 : st + 1;
        #pragma unroll
        for (int ks = 0; ks < 2; ks++) {
            int acol = ks * 16 + a8 * 8;
            uint32_t Ahf[4][4], Bhf[4][2];
            #pragma unroll
            for (int mt = 0; mt < 4; mt++) {
                uint32_t ad = tb + (uint32_t)((wm * 64 + mt * 16 + ar) * STRIDE + acol) * 2;
                ldsm4(Ahf[mt], ad);
            }
            #pragma unroll
            for (int p = 0; p < 2; p++) {
                uint32_t bd = tb + TILE_B +
                              (uint32_t)((wn * 32 + p * 16 + ar) * STRIDE + acol) * 2;
                uint32_t t[4];
                ldsm4(t, bd);
                Bhf[2*p][0] = t[0]; Bhf[2*p][1] = t[2];
                Bhf[2*p+1][0] = t[1]; Bhf[2*p+1][1] = t[3];
            }
            #pragma unroll
            for (int mt = 0; mt < 4; mt++)
                #pragma unroll
                for (int nt = 0; nt < 4; nt++)
                    mma16816h(acc[mt][nt], Ahf[mt], Bhf[nt]);
        }
    }
#undef LOADC

    int relu = flags & 1, wf = flags & 2, wh = flags & 4, addx = flags & 32;
    int r_base = m0 + wm * 64 + (lane >> 2);
    int c_base = n0 + wn * 32 + (lane & 3) * 2;
    #pragma unroll
    for (int nt = 0; nt < 4; nt++) {
        int c0 = c_base + nt * 8;
        float sc = (flags & 8) ? ((c0 < 512) ? 0.125f : 1.0f) : oscale;
        float2 bv = *(const float2*)(bias + c0);
        #pragma unroll
        for (int mt = 0; mt < 4; mt++) {
            #pragma unroll
            for (int h = 0; h < 2; h++) {
                int r = r_base + mt * 16 + h * 8;
                size_t off = (size_t)r * N + c0;
                float v0 = (acc[mt][nt][h*2+0] + bv.x) * sc;
                float v1 = (acc[mt][nt][h*2+1] + bv.y) * sc;
                if (relu) { v0 = fmaxf(v0, 0.f); v1 = fmaxf(v1, 0.f); }
                if (addx) {
                    float2 xv = *(const float2*)(X + off);
                    v0 += xv.x; v1 += xv.y;
                }
                if (wf) *(float2*)(C + off) = make_float2(v0, v1);
                if (wh) store_f16x2(Oh, off, v0, v1);
            }
        }
    }
}

// ====================== fp16 HMMA flash attention (single-term, single-sync) ======================
#define AQ_OFF    0
#define ASTG_BASE 18432
#define AK_OFF    0
#define AV_OFF    9216
#define ABK_OFF   18432
#define ASTG_SZ   26624
#define ATB_OFF   (ASTG_BASE + 2*ASTG_SZ)        // 71680
#define ATTN2_SMEM (ATB_OFF + 128)               // 71808

__device__ __forceinline__ void load_kv_tile(
    uint32_t sb, const __half* qv, const unsigned char* bkp,
    int b, int h, int q0, int kt, int st, int tid)
{
    uint32_t stb = sb + ASTG_BASE + st * ASTG_SZ;
    const char* gk = (const char*)qv + ((size_t)(b * L_) * NQKV + 512  + h * DH_) * 2;
    const char* gv = (const char*)qv + ((size_t)(b * L_) * NQKV + 1024 + h * DH_) * 2;
    #pragma unroll
    for (int i = 0; i < 2; i++) {
        int idx = tid + i * 256;
        int r = idx >> 3, c = idx & 7;
        size_t go = (size_t)(kt * 64 + r) * (NQKV * 2) + c * 16;
        uint32_t so = (uint32_t)(r * 144 + c * 16);
        cp16(stb + AK_OFF + so, gk + go);
        cp16(stb + AV_OFF + so, gv + go);
    }
    #pragma unroll
    for (int i = 0; i < 2; i++) {
        int idx = tid + i * 256;
        int r = idx >> 2, c = idx & 3;
        size_t go = ((size_t)(b * L_ + q0 + r)) * L_ + kt * 64 + c * 16;
        cp16(stb + ABK_OFF + (uint32_t)(r * 64 + c * 16), bkp + go);
    }
    asm volatile("cp.async.commit_group;");
}

__global__ __launch_bounds__(256, 2)
void attn_mma(const __half* __restrict__ qv,
              const unsigned char* __restrict__ bkp, const float* __restrict__ tbias,
              __half* __restrict__ oh)
{
    extern __shared__ char sm[];
    uint32_t sb = smem_u32(sm);
    float* smf = (float*)sm;

    int qt = (int)gridDim.x - 1 - (int)blockIdx.x;   // heavy-first
    int h = blockIdx.y, b = blockIdx.z;
    int q0 = qt * 128;
    int tid = threadIdx.x, lane = tid & 31, wid = tid >> 5;
    int g = lane >> 2, tig = lane & 3, tig2 = tig * 2;
    int ar = lane & 15, a8 = lane >> 4;

    {
        const char* gq = (const char*)qv + ((size_t)(b * L_ + q0) * NQKV + h * DH_) * 2;
        #pragma unroll
        for (int i = 0; i < 4; i++) {
            int idx = tid + i * 256;
            int r = idx >> 3, c = idx & 7;
            cp16(sb + AQ_OFF + (uint32_t)(r * 144 + c * 16),
                 gq + (size_t)r * (NQKV * 2) + c * 16);
        }
    }
    if (tid < NB_) smf[ATB_OFF/4 + tid] = tbias[tid * H_ + h];

    int nkt = 2 * qt + 2;
    load_kv_tile(sb, qv, bkp, b, h, q0, 0, 0, tid);

    int qg0 = q0 + wid * 16 + g, qg1 = qg0 + 8;
    int r0l = wid * 16 + g, r1l = r0l + 8;
    float m0 = -1e30f, m1 = -1e30f, l0 = 0.f, l1 = 0.f;
    float acc_o[8][4];
    #pragma unroll
    for (int nt = 0; nt < 8; nt++)
        #pragma unroll
        for (int i = 0; i < 4; i++) acc_o[nt][i] = 0.f;

    uint32_t qhf[4][4];
    asm volatile("cp.async.wait_group 0;");
    __syncthreads();
    #pragma unroll
    for (int kc = 0; kc < 4; kc++) {
        uint32_t ad = sb + AQ_OFF + (uint32_t)((wid * 16 + ar) * 72 + kc * 16 + a8 * 8) * 2;
        ldsm4(qhf[kc], ad);
    }

    const float* tb = (const float*)(sm + ATB_OFF);

    for (int kt = 0; kt < nkt; kt++) {
        int st = kt & 1;
        asm volatile("cp.async.wait_group 0;");
        __syncthreads();
        if (kt + 1 < nkt) load_kv_tile(sb, qv, bkp, b, h, q0, kt + 1, st ^ 1, tid);

        uint32_t stb = sb + ASTG_BASE + st * ASTG_SZ;
        const unsigned char* bkt = (const unsigned char*)(sm + ASTG_BASE + st * ASTG_SZ + ABK_OFF);

        float S[8][4];
        #pragma unroll
        for (int nt = 0; nt < 8; nt++)
            #pragma unroll
            for (int i = 0; i < 4; i++) S[nt][i] = 0.f;

        #pragma unroll
        for (int kc = 0; kc < 4; kc++) {
            #pragma unroll
            for (int nt2 = 0; nt2 < 4; nt2++) {
                uint32_t kd = stb + AK_OFF + (uint32_t)((nt2 * 16 + ar) * 72 + kc * 16 + a8 * 8) * 2;
                uint32_t th[4];
                ldsm4(th, kd);
                uint32_t b0[2] = {th[0], th[2]}, b1[2] = {th[1], th[3]};
                mma16816h(S[2*nt2],   qhf[kc], b0);
                mma16816h(S[2*nt2+1], qhf[kc], b1);
            }
        }

        bool needMask = (kt >= 2 * qt);
        float mx0 = -1e30f, mx1 = -1e30f;
        #pragma unroll
        for (int nt = 0; nt < 8; nt++) {
            int colb = nt * 8 + tig2;
            uint32_t pb0 = *(const unsigned short*)(bkt + r0l * 64 + colb);
            uint32_t pb1 = *(const unsigned short*)(bkt + r1l * 64 + colb);
            float s0a = S[nt][0] + tb[pb0 & 0xFF];
            float s0b = S[nt][1] + tb[pb0 >> 8];
            float s1a = S[nt][2] + tb[pb1 & 0xFF];
            float s1b = S[nt][3] + tb[pb1 >> 8];
            if (needMask) {
                int kg = kt * 64 + colb;
                if (kg     > qg0) s0a = -1e30f;
                if (kg + 1 > qg0) s0b = -1e30f;
                if (kg     > qg1) s1a = -1e30f;
                if (kg + 1 > qg1) s1b = -1e30f;
            }
            S[nt][0] = s0a; S[nt][1] = s0b; S[nt][2] = s1a; S[nt][3] = s1b;
            mx0 = fmaxf(mx0, fmaxf(s0a, s0b));
            mx1 = fmaxf(mx1, fmaxf(s1a, s1b));
        }
        mx0 = fmaxf(mx0, __shfl_xor_sync(~0u, mx0, 1));
        mx0 = fmaxf(mx0, __shfl_xor_sync(~0u, mx0, 2));
        mx1 = fmaxf(mx1, __shfl_xor_sync(~0u, mx1, 1));
        mx1 = fmaxf(mx1, __shfl_xor_sync(~0u, mx1, 2));
        float mn0 = fmaxf(m0, mx0), mn1 = fmaxf(m1, mx1);
        float rs0 = __expf(m0 - mn0), rs1 = __expf(m1 - mn1);
        m0 = mn0; m1 = mn1;

        float sum0 = 0.f, sum1 = 0.f;
        #pragma unroll
        for (int nt = 0; nt < 8; nt++) {
            float p0 = __expf(S[nt][0] - mn0);
            float p1 = __expf(S[nt][1] - mn0);
            float p2 = __expf(S[nt][2] - mn1);
            float p3 = __expf(S[nt][3] - mn1);
            S[nt][0] = p0; S[nt][1] = p1; S[nt][2] = p2; S[nt][3] = p3;
            sum0 += p0 + p1; sum1 += p2 + p3;
        }
        sum0 += __shfl_xor_sync(~0u, sum0, 1); sum0 += __shfl_xor_sync(~0u, sum0, 2);
        sum1 += __shfl_xor_sync(~0u, sum1, 1); sum1 += __shfl_xor_sync(~0u, sum1, 2);
        l0 = l0 * rs0 + sum0;
        l1 = l1 * rs1 + sum1;
        #pragma unroll
        for (int nt = 0; nt < 8; nt++) {
            acc_o[nt][0] *= rs0; acc_o[nt][1] *= rs0;
            acc_o[nt][2] *= rs1; acc_o[nt][3] *= rs1;
        }

        #pragma unroll
        for (int t = 0; t < 4; t++) {
            uint32_t ap[4];
            ap[0] = pack_f16(S[2*t][0],   S[2*t][1]);
            ap[1] = pack_f16(S[2*t][2],   S[2*t][3]);
            ap[2] = pack_f16(S[2*t+1][0], S[2*t+1][1]);
            ap[3] = pack_f16(S[2*t+1][2], S[2*t+1][3]);
            #pragma unroll
            for (int j2 = 0; j2 < 4; j2++) {
                uint32_t vd = stb + AV_OFF + (uint32_t)((t * 16 + ar) * 72 + j2 * 16 + a8 * 8) * 2;
                uint32_t th[4];
                ldsm4t(th, vd);
                uint32_t b0[2] = {th[0], th[1]}, b1[2] = {th[2], th[3]};
                mma16816h(acc_o[2*j2],   ap, b0);
                mma16816h(acc_o[2*j2+1], ap, b1);
            }
        }
    }

    float inv0 = 1.0f / l0, inv1 = 1.0f / l1;
    size_t row0 = ((size_t)(b * L_ + qg0)) * D_ + h * DH_;
    size_t row1 = ((size_t)(b * L_ + qg1)) * D_ + h * DH_;
    #pragma unroll
    for (int nt = 0; nt < 8; nt++) {
        int cc = nt * 8 + tig2;
        store_f16x2(oh, row0 + cc, acc_o[nt][0] * inv0, acc_o[nt][1] * inv0);
        store_f16x2(oh, row1 + cc, acc_o[nt][2] * inv1, acc_o[nt][3] * inv1);
    }
}

// ====================== single-pass LayerNorm (2 rows per 256-thread block) ======================
__global__ __launch_bounds__(256)
void ln_kernel(const float* __restrict__ xin,
               const float* __restrict__ g, const float* __restrict__ bb,
               float* __restrict__ xout, __half* __restrict__ oh, int writeH)
{
    __shared__ float sy[2][D_];
    __shared__ float2 red[2][4];
    int half = threadIdx.x >> 7;
    int tid  = threadIdx.x & 127;
    int row  = blockIdx.x * 2 + half;
    int lane = tid & 31, w = tid >> 5;

    const float* xr = xin + (size_t)row * D_;

    float lsum = 0.f, lsq = 0.f;
    #pragma unroll
    for (int i = 0; i < 4; i++) {
        int d = tid + i * 128;
        float val = xr[d];
        sy[half][d] = val;
        lsum += val;
        lsq  += val * val;
    }
    #pragma unroll
    for (int o = 16; o > 0; o >>= 1) {
        lsum += __shfl_xor_sync(~0u, lsum, o);
        lsq  += __shfl_xor_sync(~0u, lsq,  o);
    }
    if (lane == 0) red[half][w] = make_float2(lsum, lsq);
    __syncthreads();
    float2 r0 = red[half][0], r1 = red[half][1], r2 = red[half][2], r3 = red[half][3];
    float mean = (r0.x + r1.x + r2.x + r3.x) * (1.0f / D_);
    float ex2  = (r0.y + r1.y + r2.y + r3.y) * (1.0f / D_);
    float var  = ex2 - mean * mean;
    float inv  = rsqrtf(var + 1e-5f);

    #pragma unroll
    for (int i = 0; i < 4; i++) {
        int d = tid + i * 128;
        float val = (sy[half][d] - mean) * inv * g[d] + bb[d];
        xout[(size_t)row * D_ + d] = val;
        if (writeH)
            oh[(size_t)row * D_ + d] = __float2half_rn(val);
    }
}

// ====================== launch ======================
extern "C" void kernel_launch(void* const* d_in, const int* in_sizes, int n_in,
                              void* d_out, int out_size)
{
    const int*   seq      = (const int*)  d_in[0];
    const float* ts       = (const float*)d_in[1];
    const float* item_emb = (const float*)d_in[2];
    const float* pos_emb  = (const float*)d_in[3];
    const float* Wq  = (const float*)d_in[4];  const float* bq  = (const float*)d_in[5];
    const float* Wk  = (const float*)d_in[6];  const float* bk  = (const float*)d_in[7];
    const float* Wv  = (const float*)d_in[8];  const float* bv  = (const float*)d_in[9];
    const float* tbias = (const float*)d_in[10];
    const float* Wo  = (const float*)d_in[11]; const float* bo  = (const float*)d_in[12];
    const float* g1  = (const float*)d_in[13]; const float* be1 = (const float*)d_in[14];
    const float* W1  = (const float*)d_in[15]; const float* bf1 = (const float*)d_in[16];
    const float* W2  = (const float*)d_in[17]; const float* bf2 = (const float*)d_in[18];
    const float* g2  = (const float*)d_in[19]; const float* be2 = (const float*)d_in[20];

    float *x, *po, *bqkv;
    __half *ah, *fh, *qv, *wth;
    unsigned char* bkptr;
    cudaGetSymbolAddress((void**)&x,  g_x);
    cudaGetSymbolAddress((void**)&po, g_po);
    cudaGetSymbolAddress((void**)&ah, g_ah);
    cudaGetSymbolAddress((void**)&qv, g_qv);
    cudaGetSymbolAddress((void**)&fh, g_fh);
    cudaGetSymbolAddress((void**)&wth, g_wth);
    cudaGetSymbolAddress((void**)&bkptr, g_bk);
    cudaGetSymbolAddress((void**)&bqkv, g_bqkv);

    cudaFuncSetAttribute(attn_mma,  cudaFuncAttributeMaxDynamicSharedMemorySize, ATTN2_SMEM);
    cudaFuncSetAttribute(gemm_hmma, cudaFuncAttributeMaxDynamicSharedMemorySize, GSMEM);

    const size_t OQ = 0, OO = 786432, O1 = 1048576, O2 = 2097152;
    dim3 t32(32, 8);
    dim3 gQKV(NQKV / 128, ML_ / 128);  // (12, 128)
    dim3 gD(D_ / 128, ML_ / 128);      // (4, 128)
    dim3 gF(DFF_ / 128, ML_ / 128);    // (16, 128)
    dim3 ga(L_ / 128, H_, B_);         // (4, 8, 32)

    conv_wt_kernel<<<dim3(16, 16, NL_), t32>>>(Wq, wth+0,      512, 512,  (size_t)D_*D_,   WT_LAYER);
    conv_wt_kernel<<<dim3(16, 16, NL_), t32>>>(Wk, wth+262144, 512, 512,  (size_t)D_*D_,   WT_LAYER);
    conv_wt_kernel<<<dim3(16, 16, NL_), t32>>>(Wv, wth+524288, 512, 512,  (size_t)D_*D_,   WT_LAYER);
    conv_wt_kernel<<<dim3(16, 16, NL_), t32>>>(Wo, wth+OO,     512, 512,  (size_t)D_*D_,   WT_LAYER);
    conv_wt_kernel<<<dim3(64, 16, NL_), t32>>>(W1, wth+O1,     512, 2048, (size_t)D_*DFF_, WT_LAYER);
    conv_wt_kernel<<<dim3(16, 64, NL_), t32>>>(W2, wth+O2,     2048, 512, (size_t)DFF_*D_, WT_LAYER);

    biascat_kernel<<<(NL_*NQKV)/256, 256>>>(bq, bk, bv);
    embed_kernel<<<(ML_ * D_ / 4) / 256, 256>>>(seq, item_emb, pos_emb);
    bucket_kernel<<<(B_*L_*L_)/256, 256>>>(ts);

    for (int i = 0; i < NL_; i++) {
        size_t wb = (size_t)i * WT_LAYER;

        // fused QKV -> fp16 packed output, q-section scaled 0.125
        gemm_hmma<<<gQKV, 256, GSMEM>>>(ah, wth+wb+OQ, bqkv + i*NQKV,
                                        0, qv, 0, ML_, NQKV, D_, 4|8, 1.0f);

        attn_mma<<<ga, 256, ATTN2_SMEM>>>(qv, bkptr, tbias + (size_t)i*NB_*H_, ah);

        // Wo GEMM with fused residual add (po = WoOut + bias + x)
        gemm_hmma<<<gD, 256, GSMEM>>>(ah, wth+wb+OO, bo + i*D_, po, 0, x, ML_, D_, D_, 2|32, 1.0f);
        ln_kernel<<<ML_/2, 256>>>(po, g1 + i*D_, be1 + i*D_, x, ah, 1);

        gemm_hmma<<<gF, 256, GSMEM>>>(ah, wth+wb+O1, bf1 + i*DFF_, 0, fh, 0, ML_, DFF_, D_, 1|4, 1.0f);
        // FF2 GEMM with fused residual add (po = FF2Out + bias + x)
        gemm_hmma<<<gD, 256, GSMEM>>>(fh, wth+wb+O2, bf2 + i*D_, po, 0, x, ML_, D_, DFF_, 2|32, 1.0f);

        float* xo = (i == NL_ - 1) ? (float*)d_out : x;
        ln_kernel<<<ML_/2, 256>>>(po, g2 + i*D_, be2 + i*D_, xo, ah, (i < NL_ - 1) ? 1 : 0);
    }
}

// round 17
// speedup vs baseline: 1.2016x; 1.0177x over previous
#include <cuda_runtime.h>
#include <cuda_fp16.h>
#include <math.h>
#include <stdint.h>

#define B_   32
#define L_   512
#define D_   512
#define H_   8
#define DH_  64
#define NL_  2
#define DFF_ 2048
#define NB_  32
#define ML_  (B_*L_)   // 16384 rows
#define NQKV 1536

// ---------------- scratch (device globals; no allocations) ----------------
__device__ float g_x [ML_*D_];
__device__ float g_po[ML_*D_];
__device__ __align__(16) __half g_ah[ML_*D_];
__device__ __align__(16) __half g_fh[ML_*DFF_];
__device__ __align__(16) __half g_qv[ML_*NQKV];
#define WT_LAYER (4*512*512 + 2048*512 + 512*2048)
__device__ __align__(16) __half g_wth[NL_*WT_LAYER];
__device__ __align__(16) unsigned char g_bk[B_*L_*L_];
__device__ float g_bqkv[NL_*NQKV];

// ====================== PTX helpers ======================
__device__ __forceinline__ uint32_t smem_u32(const void* p) {
    uint32_t a;
    asm("{ .reg .u64 t; cvta.to.shared.u64 t, %1; cvt.u32.u64 %0, t; }" : "=r"(a) : "l"(p));
    return a;
}
__device__ __forceinline__ void cp16(uint32_t s, const void* g) {
    asm volatile("cp.async.cg.shared.global [%0], [%1], 16;" :: "r"(s), "l"(g));
}
__device__ __forceinline__ void ldsm4(uint32_t* r, uint32_t a) {
    asm volatile("ldmatrix.sync.aligned.m8n8.x4.shared.b16 {%0,%1,%2,%3}, [%4];"
        : "=r"(r[0]), "=r"(r[1]), "=r"(r[2]), "=r"(r[3]) : "r"(a));
}
__device__ __forceinline__ void ldsm4t(uint32_t* r, uint32_t a) {
    asm volatile("ldmatrix.sync.aligned.m8n8.x4.trans.shared.b16 {%0,%1,%2,%3}, [%4];"
        : "=r"(r[0]), "=r"(r[1]), "=r"(r[2]), "=r"(r[3]) : "r"(a));
}
__device__ __forceinline__ void mma16816h(float* c, const uint32_t* a, const uint32_t* b) {
    asm volatile("mma.sync.aligned.m16n8k16.row.col.f32.f16.f16.f32 "
        "{%0,%1,%2,%3}, {%4,%5,%6,%7}, {%8,%9}, {%0,%1,%2,%3};"
        : "+f"(c[0]), "+f"(c[1]), "+f"(c[2]), "+f"(c[3])
        : "r"(a[0]), "r"(a[1]), "r"(a[2]), "r"(a[3]), "r"(b[0]), "r"(b[1]));
}
__device__ __forceinline__ uint32_t pack_f16(float x, float y) {
    __half2 t = __halves2half2(__float2half_rn(x), __float2half_rn(y));
    return *(uint32_t*)&t;
}
__device__ __forceinline__ void store_f16x2(__half* O, size_t off, float v0, float v1) {
    *(uint32_t*)(O + off) = pack_f16(v0, v1);
}

// ====================== time bucket (fast lg2.approx path) ======================
__device__ __forceinline__ int time_bucket(float delta)
{
    float a = fmaxf(fabsf(delta), 1.0f);
    const float scale = 0.71018780958489f;   // float32(log2(2592000)/30)
    int idx = (int)(__log2f(a) / scale) + 1;
    idx = max(1, min(idx, NB_ - 2));
    if (a <= 1.0f)       idx = 0;
    if (a >= 2592000.0f) idx = NB_ - 1;
    return idx;
}

// ====================== fused prep kernel ======================
// segments (256 threads each):
//  [0,512)       Wq transpose    [512,1024)  Wk    [1024,1536) Wv    [1536,2048) Wo
//  [2048,4096)   W1 transpose    [4096,6144) W2
//  [6144,6156)   biascat         [6156,14348) embed   [14348,47116) bucket
#define PREP_BLOCKS 47116

__device__ __forceinline__ void conv_wt_body(const float* __restrict__ W,
                                             __half* __restrict__ Th,
                                             int K, int N, int bx, int by,
                                             int tx, int ty)
{
    __shared__ float s[32][33];
    int n0 = bx * 32, k0 = by * 32;
    #pragma unroll
    for (int j = 0; j < 32; j += 8)
        s[ty + j][tx] = W[(size_t)(k0 + ty + j) * N + n0 + tx];
    __syncthreads();
    #pragma unroll
    for (int j = 0; j < 32; j += 8) {
        int n = n0 + ty + j, k = k0 + tx;
        Th[(size_t)n * K + k] = __float2half_rn(s[tx][ty + j]);
    }
}

__global__ __launch_bounds__(256)
void prep_kernel(const int* __restrict__ seq, const float* __restrict__ ts,
                 const float* __restrict__ item_emb, const float* __restrict__ pos_emb,
                 const float* __restrict__ Wq, const float* __restrict__ Wk,
                 const float* __restrict__ Wv, const float* __restrict__ Wo,
                 const float* __restrict__ W1, const float* __restrict__ W2,
                 const float* __restrict__ bq, const float* __restrict__ bk,
                 const float* __restrict__ bv)
{
    int bid = blockIdx.x;
    int t = threadIdx.x;
    const size_t OO = 786432, O1 = 1048576, O2 = 2097152;

    if (bid < 2048) {
        // 512x512 transposes: Wq/Wk/Wv/Wo, each 512 blocks (2 layers x 256)
        int seg = bid >> 9, local = bid & 511;
        int z = local >> 8, r = local & 255;
        int bx = r & 15, by = r >> 4;
        const float* W = (seg == 0 ? Wq : seg == 1 ? Wk : seg == 2 ? Wv : Wo)
                         + (size_t)z * D_ * D_;
        size_t oseg = (seg == 3) ? OO : (size_t)seg * 262144;
        conv_wt_body(W, g_wth + (size_t)z * WT_LAYER + oseg, 512, 512,
                     bx, by, t & 31, t >> 5);
    } else if (bid < 4096) {
        // W1 transpose [512,2048]: 2048 blocks (2 layers x 1024; grid 64x16)
        int local = bid - 2048;
        int z = local >> 10, r = local & 1023;
        int bx = r & 63, by = r >> 6;
        conv_wt_body(W1 + (size_t)z * D_ * DFF_, g_wth + (size_t)z * WT_LAYER + O1,
                     512, 2048, bx, by, t & 31, t >> 5);
    } else if (bid < 6144) {
        // W2 transpose [2048,512]: 2048 blocks (2 layers x 1024; grid 16x64)
        int local = bid - 4096;
        int z = local >> 10, r = local & 1023;
        int bx = r & 15, by = r >> 4;
        conv_wt_body(W2 + (size_t)z * DFF_ * D_, g_wth + (size_t)z * WT_LAYER + O2,
                     2048, 512, bx, by, t & 31, t >> 5);
    } else if (bid < 6156) {
        // biascat: 12 blocks over NL*1536
        int i = (bid - 6144) * 256 + t;
        int l = i / NQKV, c = i % NQKV;
        float v = (c < 512) ? bq[l*512 + c]
                : (c < 1024 ? bk[l*512 + c - 512] : bv[l*512 + c - 1024]);
        g_bqkv[i] = v;
    } else if (bid < 14348) {
        // embed: 8192 blocks over ML*D/4
        int idx = (bid - 6156) * 256 + t;
        int d4 = idx & (D_/4 - 1);
        int bl = idx >> 7;
        int l  = bl & (L_-1);
        int it = seq[bl];
        float4 a = *(const float4*)(item_emb + (size_t)it * D_ + d4*4);
        float4 p = *(const float4*)(pos_emb  + (size_t)l  * D_ + d4*4);
        a.x += p.x; a.y += p.y; a.z += p.z; a.w += p.w;
        ((float4*)g_x)[idx] = a;
        size_t off = (size_t)idx * 4;
        store_f16x2(g_ah, off,     a.x, a.y);
        store_f16x2(g_ah, off + 2, a.z, a.w);
    } else {
        // bucket: 32768 blocks over B*L*L
        int idx = (bid - 14348) * 256 + t;
        int k = idx & (L_-1);
        int q = (idx >> 9) & (L_-1);
        int b = idx >> 18;
        float d = ts[b * L_ + q] - ts[b * L_ + k];
        g_bk[idx] = (unsigned char)time_bucket(d);
    }
}

// ====================== fp16 HMMA GEMM (K-chunk 32, 3-stage, single-sync) ======================
#define TILE_B   10240
#define STAGE_B  20480   // 2 tiles (A, B)
#define GSMEM    61440   // 3 stages
#define STRIDE   40

// flags: 1 = relu, 2 = write fp32 C, 4 = write fp16 (Oh), 8 = qkv col-scale, 32 = add X residual
__global__ __launch_bounds__(256, 2)
void gemm_hmma(const __half* __restrict__ Ah, const __half* __restrict__ Bh,
               const float* __restrict__ bias, float* __restrict__ C,
               __half* __restrict__ Oh, const float* __restrict__ X,
               int M, int N, int K, int flags, float oscale)
{
    extern __shared__ char sm[];
    uint32_t sb = smem_u32(sm);
    int tid = threadIdx.x, lane = tid & 31, wid = tid >> 5;
    int wm = wid & 1, wn = wid >> 1;
    int m0 = blockIdx.y * 128, n0 = blockIdx.x * 128;

    int lrow = tid >> 2, lseg = tid & 3;
    const char* gAh = (const char*)(Ah + (size_t)(m0 + lrow) * K + lseg * 8);
    const char* gBh = (const char*)(Bh + (size_t)(n0 + lrow) * K + lseg * 8);
    size_t rowskip = (size_t)64 * K * 2;
    uint32_t s0off = (uint32_t)(lrow * STRIDE + lseg * 8) * 2;
    uint32_t s1off = s0off + 64 * STRIDE * 2;

    float acc[4][4][4];
    #pragma unroll
    for (int a = 0; a < 4; a++)
        #pragma unroll
        for (int b = 0; b < 4; b++)
            #pragma unroll
            for (int c = 0; c < 4; c++) acc[a][b][c] = 0.f;

    int NC = K >> 5;

#define LOADC(cc, st) do { \
    size_t ko = (size_t)(cc) * 64; \
    uint32_t s0 = sb + (st) * STAGE_B + s0off; \
    uint32_t s1 = sb + (st) * STAGE_B + s1off; \
    cp16(s0,          gAh + ko); cp16(s1,          gAh + ko + rowskip); \
    cp16(s0 + TILE_B, gBh + ko); cp16(s1 + TILE_B, gBh + ko + rowskip); \
    asm volatile("cp.async.commit_group;"); \
} while (0)

    LOADC(0, 0);
    LOADC(1, 1);

    int ar = lane & 15, a8 = lane >> 4;
    int st = 0;

    for (int c = 0; c < NC; c++) {
        if (c + 1 < NC) {
            asm volatile("cp.async.wait_group 1;");
        } else {
            asm volatile("cp.async.wait_group 0;");
        }
        __syncthreads();
        if (c + 2 < NC) LOADC(c + 2, (c + 2) % 3);

        uint32_t tb = sb + st * STAGE_B;
        st = (st + 1 == 3) ? 0 : st + 1;
        #pragma unroll
        for (int ks = 0; ks < 2; ks++) {
            int acol = ks * 16 + a8 * 8;
            uint32_t Ahf[4][4], Bhf[4][2];
            #pragma unroll
            for (int mt = 0; mt < 4; mt++) {
                uint32_t ad = tb + (uint32_t)((wm * 64 + mt * 16 + ar) * STRIDE + acol) * 2;
                ldsm4(Ahf[mt], ad);
            }
            #pragma unroll
            for (int p = 0; p < 2; p++) {
                uint32_t bd = tb + TILE_B +
                              (uint32_t)((wn * 32 + p * 16 + ar) * STRIDE + acol) * 2;
                uint32_t t[4];
                ldsm4(t, bd);
                Bhf[2*p][0] = t[0]; Bhf[2*p][1] = t[2];
                Bhf[2*p+1][0] = t[1]; Bhf[2*p+1][1] = t[3];
            }
            #pragma unroll
            for (int mt = 0; mt < 4; mt++)
                #pragma unroll
                for (int nt = 0; nt < 4; nt++)
                    mma16816h(acc[mt][nt], Ahf[mt], Bhf[nt]);
        }
    }
#undef LOADC

    int relu = flags & 1, wf = flags & 2, wh = flags & 4, addx = flags & 32;
    int r_base = m0 + wm * 64 + (lane >> 2);
    int c_base = n0 + wn * 32 + (lane & 3) * 2;
    #pragma unroll
    for (int nt = 0; nt < 4; nt++) {
        int c0 = c_base + nt * 8;
        float sc = (flags & 8) ? ((c0 < 512) ? 0.125f : 1.0f) : oscale;
        float2 bv = *(const float2*)(bias + c0);
        #pragma unroll
        for (int mt = 0; mt < 4; mt++) {
            #pragma unroll
            for (int h = 0; h < 2; h++) {
                int r = r_base + mt * 16 + h * 8;
                size_t off = (size_t)r * N + c0;
                float v0 = (acc[mt][nt][h*2+0] + bv.x) * sc;
                float v1 = (acc[mt][nt][h*2+1] + bv.y) * sc;
                if (relu) { v0 = fmaxf(v0, 0.f); v1 = fmaxf(v1, 0.f); }
                if (addx) {
                    float2 xv = *(const float2*)(X + off);
                    v0 += xv.x; v1 += xv.y;
                }
                if (wf) *(float2*)(C + off) = make_float2(v0, v1);
                if (wh) store_f16x2(Oh, off, v0, v1);
            }
        }
    }
}

// ====================== fp16 HMMA flash attention (single-term, single-sync) ======================
#define AQ_OFF    0
#define ASTG_BASE 18432
#define AK_OFF    0
#define AV_OFF    9216
#define ABK_OFF   18432
#define ASTG_SZ   26624
#define ATB_OFF   (ASTG_BASE + 2*ASTG_SZ)        // 71680
#define ATTN2_SMEM (ATB_OFF + 128)               // 71808

__device__ __forceinline__ void load_kv_tile(
    uint32_t sb, const __half* qv, const unsigned char* bkp,
    int b, int h, int q0, int kt, int st, int tid)
{
    uint32_t stb = sb + ASTG_BASE + st * ASTG_SZ;
    const char* gk = (const char*)qv + ((size_t)(b * L_) * NQKV + 512  + h * DH_) * 2;
    const char* gv = (const char*)qv + ((size_t)(b * L_) * NQKV + 1024 + h * DH_) * 2;
    #pragma unroll
    for (int i = 0; i < 2; i++) {
        int idx = tid + i * 256;
        int r = idx >> 3, c = idx & 7;
        size_t go = (size_t)(kt * 64 + r) * (NQKV * 2) + c * 16;
        uint32_t so = (uint32_t)(r * 144 + c * 16);
        cp16(stb + AK_OFF + so, gk + go);
        cp16(stb + AV_OFF + so, gv + go);
    }
    #pragma unroll
    for (int i = 0; i < 2; i++) {
        int idx = tid + i * 256;
        int r = idx >> 2, c = idx & 3;
        size_t go = ((size_t)(b * L_ + q0 + r)) * L_ + kt * 64 + c * 16;
        cp16(stb + ABK_OFF + (uint32_t)(r * 64 + c * 16), bkp + go);
    }
    asm volatile("cp.async.commit_group;");
}

__global__ __launch_bounds__(256, 2)
void attn_mma(const __half* __restrict__ qv,
              const unsigned char* __restrict__ bkp, const float* __restrict__ tbias,
              __half* __restrict__ oh)
{
    extern __shared__ char sm[];
    uint32_t sb = smem_u32(sm);
    float* smf = (float*)sm;

    int qt = (int)gridDim.x - 1 - (int)blockIdx.x;   // heavy-first
    int h = blockIdx.y, b = blockIdx.z;
    int q0 = qt * 128;
    int tid = threadIdx.x, lane = tid & 31, wid = tid >> 5;
    int g = lane >> 2, tig = lane & 3, tig2 = tig * 2;
    int ar = lane & 15, a8 = lane >> 4;

    {
        const char* gq = (const char*)qv + ((size_t)(b * L_ + q0) * NQKV + h * DH_) * 2;
        #pragma unroll
        for (int i = 0; i < 4; i++) {
            int idx = tid + i * 256;
            int r = idx >> 3, c = idx & 7;
            cp16(sb + AQ_OFF + (uint32_t)(r * 144 + c * 16),
                 gq + (size_t)r * (NQKV * 2) + c * 16);
        }
    }
    if (tid < NB_) smf[ATB_OFF/4 + tid] = tbias[tid * H_ + h];

    int nkt = 2 * qt + 2;
    load_kv_tile(sb, qv, bkp, b, h, q0, 0, 0, tid);

    int qg0 = q0 + wid * 16 + g, qg1 = qg0 + 8;
    int r0l = wid * 16 + g, r1l = r0l + 8;
    float m0 = -1e30f, m1 = -1e30f, l0 = 0.f, l1 = 0.f;
    float acc_o[8][4];
    #pragma unroll
    for (int nt = 0; nt < 8; nt++)
        #pragma unroll
        for (int i = 0; i < 4; i++) acc_o[nt][i] = 0.f;

    uint32_t qhf[4][4];
    asm volatile("cp.async.wait_group 0;");
    __syncthreads();
    #pragma unroll
    for (int kc = 0; kc < 4; kc++) {
        uint32_t ad = sb + AQ_OFF + (uint32_t)((wid * 16 + ar) * 72 + kc * 16 + a8 * 8) * 2;
        ldsm4(qhf[kc], ad);
    }

    const float* tb = (const float*)(sm + ATB_OFF);

    for (int kt = 0; kt < nkt; kt++) {
        int st = kt & 1;
        asm volatile("cp.async.wait_group 0;");
        __syncthreads();
        if (kt + 1 < nkt) load_kv_tile(sb, qv, bkp, b, h, q0, kt + 1, st ^ 1, tid);

        uint32_t stb = sb + ASTG_BASE + st * ASTG_SZ;
        const unsigned char* bkt = (const unsigned char*)(sm + ASTG_BASE + st * ASTG_SZ + ABK_OFF);

        float S[8][4];
        #pragma unroll
        for (int nt = 0; nt < 8; nt++)
            #pragma unroll
            for (int i = 0; i < 4; i++) S[nt][i] = 0.f;

        #pragma unroll
        for (int kc = 0; kc < 4; kc++) {
            #pragma unroll
            for (int nt2 = 0; nt2 < 4; nt2++) {
                uint32_t kd = stb + AK_OFF + (uint32_t)((nt2 * 16 + ar) * 72 + kc * 16 + a8 * 8) * 2;
                uint32_t th[4];
                ldsm4(th, kd);
                uint32_t b0[2] = {th[0], th[2]}, b1[2] = {th[1], th[3]};
                mma16816h(S[2*nt2],   qhf[kc], b0);
                mma16816h(S[2*nt2+1], qhf[kc], b1);
            }
        }

        bool needMask = (kt >= 2 * qt);
        float mx0 = -1e30f, mx1 = -1e30f;
        #pragma unroll
        for (int nt = 0; nt < 8; nt++) {
            int colb = nt * 8 + tig2;
            uint32_t pb0 = *(const unsigned short*)(bkt + r0l * 64 + colb);
            uint32_t pb1 = *(const unsigned short*)(bkt + r1l * 64 + colb);
            float s0a = S[nt][0] + tb[pb0 & 0xFF];
            float s0b = S[nt][1] + tb[pb0 >> 8];
            float s1a = S[nt][2] + tb[pb1 & 0xFF];
            float s1b = S[nt][3] + tb[pb1 >> 8];
            if (needMask) {
                int kg = kt * 64 + colb;
                if (kg     > qg0) s0a = -1e30f;
                if (kg + 1 > qg0) s0b = -1e30f;
                if (kg     > qg1) s1a = -1e30f;
                if (kg + 1 > qg1) s1b = -1e30f;
            }
            S[nt][0] = s0a; S[nt][1] = s0b; S[nt][2] = s1a; S[nt][3] = s1b;
            mx0 = fmaxf(mx0, fmaxf(s0a, s0b));
            mx1 = fmaxf(mx1, fmaxf(s1a, s1b));
        }
        mx0 = fmaxf(mx0, __shfl_xor_sync(~0u, mx0, 1));
        mx0 = fmaxf(mx0, __shfl_xor_sync(~0u, mx0, 2));
        mx1 = fmaxf(mx1, __shfl_xor_sync(~0u, mx1, 1));
        mx1 = fmaxf(mx1, __shfl_xor_sync(~0u, mx1, 2));
        float mn0 = fmaxf(m0, mx0), mn1 = fmaxf(m1, mx1);
        float rs0 = __expf(m0 - mn0), rs1 = __expf(m1 - mn1);
        m0 = mn0; m1 = mn1;

        float sum0 = 0.f, sum1 = 0.f;
        #pragma unroll
        for (int nt = 0; nt < 8; nt++) {
            float p0 = __expf(S[nt][0] - mn0);
            float p1 = __expf(S[nt][1] - mn0);
            float p2 = __expf(S[nt][2] - mn1);
            float p3 = __expf(S[nt][3] - mn1);
            S[nt][0] = p0; S[nt][1] = p1; S[nt][2] = p2; S[nt][3] = p3;
            sum0 += p0 + p1; sum1 += p2 + p3;
        }
        sum0 += __shfl_xor_sync(~0u, sum0, 1); sum0 += __shfl_xor_sync(~0u, sum0, 2);
        sum1 += __shfl_xor_sync(~0u, sum1, 1); sum1 += __shfl_xor_sync(~0u, sum1, 2);
        l0 = l0 * rs0 + sum0;
        l1 = l1 * rs1 + sum1;
        #pragma unroll
        for (int nt = 0; nt < 8; nt++) {
            acc_o[nt][0] *= rs0; acc_o[nt][1] *= rs0;
            acc_o[nt][2] *= rs1; acc_o[nt][3] *= rs1;
        }

        #pragma unroll
        for (int t = 0; t < 4; t++) {
            uint32_t ap[4];
            ap[0] = pack_f16(S[2*t][0],   S[2*t][1]);
            ap[1] = pack_f16(S[2*t][2],   S[2*t][3]);
            ap[2] = pack_f16(S[2*t+1][0], S[2*t+1][1]);
            ap[3] = pack_f16(S[2*t+1][2], S[2*t+1][3]);
            #pragma unroll
            for (int j2 = 0; j2 < 4; j2++) {
                uint32_t vd = stb + AV_OFF + (uint32_t)((t * 16 + ar) * 72 + j2 * 16 + a8 * 8) * 2;
                uint32_t th[4];
                ldsm4t(th, vd);
                uint32_t b0[2] = {th[0], th[1]}, b1[2] = {th[2], th[3]};
                mma16816h(acc_o[2*j2],   ap, b0);
                mma16816h(acc_o[2*j2+1], ap, b1);
            }
        }
    }

    float inv0 = 1.0f / l0, inv1 = 1.0f / l1;
    size_t row0 = ((size_t)(b * L_ + qg0)) * D_ + h * DH_;
    size_t row1 = ((size_t)(b * L_ + qg1)) * D_ + h * DH_;
    #pragma unroll
    for (int nt = 0; nt < 8; nt++) {
        int cc = nt * 8 + tig2;
        store_f16x2(oh, row0 + cc, acc_o[nt][0] * inv0, acc_o[nt][1] * inv0);
        store_f16x2(oh, row1 + cc, acc_o[nt][2] * inv1, acc_o[nt][3] * inv1);
    }
}

// ====================== single-pass LayerNorm (2 rows per 256-thread block) ======================
__global__ __launch_bounds__(256)
void ln_kernel(const float* __restrict__ xin,
               const float* __restrict__ g, const float* __restrict__ bb,
               float* __restrict__ xout, __half* __restrict__ oh, int writeH)
{
    __shared__ float sy[2][D_];
    __shared__ float2 red[2][4];
    int half = threadIdx.x >> 7;
    int tid  = threadIdx.x & 127;
    int row  = blockIdx.x * 2 + half;
    int lane = tid & 31, w = tid >> 5;

    const float* xr = xin + (size_t)row * D_;

    float lsum = 0.f, lsq = 0.f;
    #pragma unroll
    for (int i = 0; i < 4; i++) {
        int d = tid + i * 128;
        float val = xr[d];
        sy[half][d] = val;
        lsum += val;
        lsq  += val * val;
    }
    #pragma unroll
    for (int o = 16; o > 0; o >>= 1) {
        lsum += __shfl_xor_sync(~0u, lsum, o);
        lsq  += __shfl_xor_sync(~0u, lsq,  o);
    }
    if (lane == 0) red[half][w] = make_float2(lsum, lsq);
    __syncthreads();
    float2 r0 = red[half][0], r1 = red[half][1], r2 = red[half][2], r3 = red[half][3];
    float mean = (r0.x + r1.x + r2.x + r3.x) * (1.0f / D_);
    float ex2  = (r0.y + r1.y + r2.y + r3.y) * (1.0f / D_);
    float var  = ex2 - mean * mean;
    float inv  = rsqrtf(var + 1e-5f);

    #pragma unroll
    for (int i = 0; i < 4; i++) {
        int d = tid + i * 128;
        float val = (sy[half][d] - mean) * inv * g[d] + bb[d];
        xout[(size_t)row * D_ + d] = val;
        if (writeH)
            oh[(size_t)row * D_ + d] = __float2half_rn(val);
    }
}

// ====================== launch ======================
extern "C" void kernel_launch(void* const* d_in, const int* in_sizes, int n_in,
                              void* d_out, int out_size)
{
    const int*   seq      = (const int*)  d_in[0];
    const float* ts       = (const float*)d_in[1];
    const float* item_emb = (const float*)d_in[2];
    const float* pos_emb  = (const float*)d_in[3];
    const float* Wq  = (const float*)d_in[4];  const float* bq  = (const float*)d_in[5];
    const float* Wk  = (const float*)d_in[6];  const float* bk  = (const float*)d_in[7];
    const float* Wv  = (const float*)d_in[8];  const float* bv  = (const float*)d_in[9];
    const float* tbias = (const float*)d_in[10];
    const float* Wo  = (const float*)d_in[11]; const float* bo  = (const float*)d_in[12];
    const float* g1  = (const float*)d_in[13]; const float* be1 = (const float*)d_in[14];
    const float* W1  = (const float*)d_in[15]; const float* bf1 = (const float*)d_in[16];
    const float* W2  = (const float*)d_in[17]; const float* bf2 = (const float*)d_in[18];
    const float* g2  = (const float*)d_in[19]; const float* be2 = (const float*)d_in[20];

    float *x, *po, *bqkv;
    __half *ah, *fh, *qv, *wth;
    unsigned char* bkptr;
    cudaGetSymbolAddress((void**)&x,  g_x);
    cudaGetSymbolAddress((void**)&po, g_po);
    cudaGetSymbolAddress((void**)&ah, g_ah);
    cudaGetSymbolAddress((void**)&qv, g_qv);
    cudaGetSymbolAddress((void**)&fh, g_fh);
    cudaGetSymbolAddress((void**)&wth, g_wth);
    cudaGetSymbolAddress((void**)&bkptr, g_bk);
    cudaGetSymbolAddress((void**)&bqkv, g_bqkv);

    cudaFuncSetAttribute(attn_mma,  cudaFuncAttributeMaxDynamicSharedMemorySize, ATTN2_SMEM);
    cudaFuncSetAttribute(gemm_hmma, cudaFuncAttributeMaxDynamicSharedMemorySize, GSMEM);

    const size_t OQ = 0, OO = 786432, O1 = 1048576, O2 = 2097152;
    dim3 gQKV(NQKV / 128, ML_ / 128);  // (12, 128)
    dim3 gD(D_ / 128, ML_ / 128);      // (4, 128)
    dim3 gF(DFF_ / 128, ML_ / 128);    // (16, 128)
    dim3 ga(L_ / 128, H_, B_);         // (4, 8, 32)

    // single fused prep launch: all transposes + biascat + embed + bucket
    prep_kernel<<<PREP_BLOCKS, 256>>>(seq, ts, item_emb, pos_emb,
                                      Wq, Wk, Wv, Wo, W1, W2, bq, bk, bv);

    for (int i = 0; i < NL_; i++) {
        size_t wb = (size_t)i * WT_LAYER;

        // fused QKV -> fp16 packed output, q-section scaled 0.125
        gemm_hmma<<<gQKV, 256, GSMEM>>>(ah, wth+wb+OQ, bqkv + i*NQKV,
                                        0, qv, 0, ML_, NQKV, D_, 4|8, 1.0f);

        attn_mma<<<ga, 256, ATTN2_SMEM>>>(qv, bkptr, tbias + (size_t)i*NB_*H_, ah);

        // Wo GEMM with fused residual add (po = WoOut + bias + x)
        gemm_hmma<<<gD, 256, GSMEM>>>(ah, wth+wb+OO, bo + i*D_, po, 0, x, ML_, D_, D_, 2|32, 1.0f);
        ln_kernel<<<ML_/2, 256>>>(po, g1 + i*D_, be1 + i*D_, x, ah, 1);

        gemm_hmma<<<gF, 256, GSMEM>>>(ah, wth+wb+O1, bf1 + i*DFF_, 0, fh, 0, ML_, DFF_, D_, 1|4, 1.0f);
        // FF2 GEMM with fused residual add (po = FF2Out + bias + x)
        gemm_hmma<<<gD, 256, GSMEM>>>(fh, wth+wb+O2, bf2 + i*D_, po, 0, x, ML_, D_, DFF_, 2|32, 1.0f);

        float* xo = (i == NL_ - 1) ? (float*)d_out : x;
        ln_kernel<<<ML_/2, 256>>>(po, g2 + i*D_, be2 + i*D_, xo, ah, (i < NL_ - 1) ? 1 : 0);
    }
}